// round 12
// baseline (speedup 1.0000x reference)
#include <cuda_runtime.h>
#include <cuda_bf16.h>
#include <cstdint>

// ---------------------------------------------------------------------------
// ConvLSTM via mma.sync bf16 (hi/lo split, 3 MMAs ~ fp32 accuracy), sm_103a.
// R12: N=128 px per CTA (2 image rows, 512 thr / 16 warps, 8Mx2N warp grid),
// pre-permuted weight pair arrays -> uint4 A staging, K-chunks of 32,
// pair-plane (pre-split packed bf16x2) states as in R11.
// ---------------------------------------------------------------------------

#define HSZ   (16 * 64 * 64 * 64)     // planar float cell state [b][64][4096]
#define PLSZ  (16 * 32 * 4096)        // pair planes [b][32][4096] (u32)

__device__ float    g_c0[HSZ], g_c1[HSZ];
__device__ uint32_t g_h0h[2][PLSZ], g_h0l[2][PLSZ];
__device__ uint32_t g_h1h[2][PLSZ], g_h1l[2][PLSZ];
__device__ uint32_t g_xph[16 * 16 * 4096], g_xpl[16 * 16 * 4096]; // [t][b][px]

// pre-permuted packed weight pairs: [chunk][row 256][pos 16] (u32 each)
#define NCH0 19
#define NCH1 36
__device__ uint32_t g_wh0[NCH0 * 4096], g_wl0[NCH0 * 4096];
__device__ uint32_t g_wh1[NCH1 * 4096], g_wl1[NCH1 * 4096];

__device__ __forceinline__ float fsig(float x) { return 1.f / (1.f + __expf(-x)); }
__device__ __forceinline__ float ftanh(float x) {
    return 2.f / (1.f + __expf(-2.f * x)) - 1.f;
}

__device__ __forceinline__ uint32_t pack_hl(float v0, float v1, uint32_t& lo) {
    __nv_bfloat16 h0 = __float2bfloat16(v0);
    __nv_bfloat16 h1 = __float2bfloat16(v1);
    float r0 = v0 - __bfloat162float(h0);
    float r1 = v1 - __bfloat162float(h1);
    lo = (uint32_t)__bfloat16_as_ushort(__float2bfloat16(r0))
       | ((uint32_t)__bfloat16_as_ushort(__float2bfloat16(r1)) << 16);
    return (uint32_t)__bfloat16_as_ushort(h0)
         | ((uint32_t)__bfloat16_as_ushort(h1) << 16);
}
__device__ __forceinline__ float bflo(uint32_t u) {
    return __bfloat162float(__ushort_as_bfloat16((unsigned short)(u & 0xffff)));
}
__device__ __forceinline__ float bfhi(uint32_t u) {
    return __bfloat162float(__ushort_as_bfloat16((unsigned short)(u >> 16)));
}

#define MMA16816(Cr, Ar, Br) \
    asm volatile("mma.sync.aligned.m16n8k16.row.col.f32.bf16.bf16.f32 " \
        "{%0,%1,%2,%3}, {%4,%5,%6,%7}, {%8,%9}, {%0,%1,%2,%3};" \
        : "+f"((Cr)[0]), "+f"((Cr)[1]), "+f"((Cr)[2]), "+f"((Cr)[3]) \
        : "r"((Ar)[0]), "r"((Ar)[1]), "r"((Ar)[2]), "r"((Ar)[3]), \
          "r"((Br)[0]), "r"((Br)[1]))

// pos p (0..15) -> pair-in-chunk u (k-permutation per k16 group)
__device__ __forceinline__ int pos2u(int p) {
    int kk = p >> 3, pw = p & 7;
    return 8 * kk + (pw >> 1) + ((pw & 1) << 2);
}

// ------------------------------ prep kernels --------------------------------

__global__ void zero_state_kernel() {
    int i = blockIdx.x * blockDim.x + threadIdx.x;
    if (i < HSZ) { g_c0[i] = 0.f; g_c1[i] = 0.f; }
    if (i < PLSZ) {
        g_h0h[0][i] = 0u; g_h0l[0][i] = 0u;
        g_h1h[0][i] = 0u; g_h1l[0][i] = 0u;
    }
}

__global__ void build_xpairs(const float* __restrict__ x) {
    int idx = blockIdx.x * blockDim.x + threadIdx.x;   // 16*16*4096
    int t  = idx >> 16;
    int b  = (idx >> 12) & 15;
    int px = idx & 4095;
    float v = x[(((size_t)b * 16 + t) << 12) + px];
    uint32_t lo;
    uint32_t hi = pack_hl(v, 0.f, lo);
    g_xph[idx] = hi;
    g_xpl[idx] = lo;
}

// layer0: global pair gu: kt=gu/33, j=gu%33; j<32 -> ic(1+2j, 2+2j); j==32 -> (0,-)
__global__ void build_w0k(const float* __restrict__ W) {
    int idx = blockIdx.x * blockDim.x + threadIdx.x;   // NCH0*4096
    if (idx >= NCH0 * 4096) return;
    int p  = idx & 15;
    int oc = (idx >> 4) & 255;
    int c  = idx >> 12;
    int gu = c * 16 + pos2u(p);
    float v0 = 0.f, v1 = 0.f;
    if (gu < 297) {
        int kt = gu / 33, j = gu - kt * 33;
        if (j < 32) {
            v0 = W[((size_t)oc * 65 + (1 + 2 * j)) * 9 + kt];
            v1 = W[((size_t)oc * 65 + (2 + 2 * j)) * 9 + kt];
        } else {
            v0 = W[((size_t)oc * 65 + 0) * 9 + kt];
        }
    }
    uint32_t lo;
    uint32_t hi = pack_hl(v0, v1, lo);
    g_wh0[idx] = hi;
    g_wl0[idx] = lo;
}

// layer1: gu: kt=gu>>6, j=gu&63 -> ic (2j, 2j+1)
__global__ void build_w1k(const float* __restrict__ W) {
    int idx = blockIdx.x * blockDim.x + threadIdx.x;   // NCH1*4096
    if (idx >= NCH1 * 4096) return;
    int p  = idx & 15;
    int oc = (idx >> 4) & 255;
    int c  = idx >> 12;
    int gu = c * 16 + pos2u(p);
    int kt = gu >> 6, j = gu & 63;
    float v0 = W[((size_t)oc * 128 + 2 * j) * 9 + kt];
    float v1 = W[((size_t)oc * 128 + 2 * j + 1) * 9 + kt];
    uint32_t lo;
    uint32_t hi = pack_hl(v0, v1, lo);
    g_wh1[idx] = hi;
    g_wl1[idx] = lo;
}

// ------------------------------ main kernel ---------------------------------
// SMEM (u32 units), pitch 20 per row (16 pos + pad, 16B-aligned):
//   AsH buf0 @0 (5120), buf1 @5120 ; AsL @10240, @15360      (256 rows)
//   BsH @20480 (2560), @23040 ; BsL @25600, @28160           (128 px)
// epilogue float sep[256][129] unions over everything.
#define DYN_SMEM (256 * 129 * 4)

template <int LAYER>
__global__ void __launch_bounds__(512, 1)
convlstm_mma(const uint32_t* __restrict__ Wh, const uint32_t* __restrict__ Wl,
             const uint32_t* __restrict__ pAh, const uint32_t* __restrict__ pAl,
             const uint32_t* __restrict__ pBh, const uint32_t* __restrict__ pBl,
             const float* __restrict__ bias,
             float* __restrict__ C,
             uint32_t* __restrict__ oH, uint32_t* __restrict__ oL)
{
    constexpr int PPT = (LAYER == 0) ? 33 : 64;    // pairs per tap
    constexpr int NCH = (LAYER == 0) ? NCH0 : NCH1;
    extern __shared__ uint32_t sm[];
    float* sep = (float*)sm;

    const int tid  = threadIdx.x;
    const int wid  = tid >> 5;
    const int lid  = tid & 31;
    const int wid8 = wid & 7;       // M group (rows wid8*32)
    const int ng   = wid >> 3;      // N group (cols ng*64)
    const int g    = lid >> 2;
    const int t4   = lid & 3;
    const int b    = blockIdx.y;
    const int y0   = blockIdx.x;    // 2-row group: image rows y0*2, y0*2+1

    float acc[2][8][4];
#pragma unroll
    for (int i = 0; i < 2; i++)
#pragma unroll
        for (int j = 0; j < 8; j++)
#pragma unroll
            for (int k = 0; k < 4; k++) acc[i][j][k] = 0.f;

    // B staging identity
    const int bpx = tid & 127;          // pixel 0..127
    const int bu  = tid >> 7;           // 0..3
    const int byr = bpx >> 6;           // row within 2-row group
    const int bx  = bpx & 63;

    // A staging identity: row = tid>>1, p0 = (tid&1)*8
    const int arow = tid >> 1;
    const int ap0  = (tid & 1) * 8;

    for (int c = 0; c < NCH + 1; c++) {
        if (c < NCH) {
            const int buf = c & 1;
            // ---- A: pre-permuted, 2x uint4 LDG + 2x STS.128 per hi/lo ----
            {
                const uint4* sH = (const uint4*)(Wh + (size_t)c * 4096) + tid * 2;
                const uint4* sL = (const uint4*)(Wl + (size_t)c * 4096) + tid * 2;
                uint4 h0 = sH[0], h1 = sH[1];
                uint4 l0 = sL[0], l1 = sL[1];
                uint4* dH = (uint4*)(sm + buf * 5120 + arow * 20 + ap0);
                uint4* dL = (uint4*)(sm + 10240 + buf * 5120 + arow * 20 + ap0);
                dH[0] = h0; dH[1] = h1;
                dL[0] = l0; dL[1] = l1;
            }
            // ---- B: 4 pos per thread, predicated LDG.32 from pair planes ----
            {
                uint32_t* bH = sm + 20480 + buf * 2560 + bpx * 20;
                uint32_t* bL = sm + 25600 + buf * 2560 + bpx * 20;
#pragma unroll
                for (int s = 0; s < 4; s++) {
                    const int p  = bu + 4 * s;
                    const int u  = pos2u(p);
                    const int gu = c * 16 + u;
                    const int kt = gu / PPT;      // may be 9 on l0 pad: weight=0
                    const int j  = gu - kt * PPT;
                    const int ky = kt / 3;
                    const int kx = kt - ky * 3;
                    const int y  = y0 * 2 + byr + ky - 1;
                    const int x  = bx + kx - 1;
                    const bool ok = ((unsigned)y < 64u) && ((unsigned)x < 64u);
                    const int poff = y * 64 + x;
                    const uint32_t* sH;
                    const uint32_t* sL;
                    if (j < 32) {
                        sH = pAh + ((size_t)(b * 32 + j) << 12);
                        sL = pAl + ((size_t)(b * 32 + j) << 12);
                    } else if (LAYER == 0) {
                        sH = pBh + ((size_t)b << 12);
                        sL = pBl + ((size_t)b << 12);
                    } else {
                        sH = pBh + ((size_t)(b * 32 + j - 32) << 12);
                        sL = pBl + ((size_t)(b * 32 + j - 32) << 12);
                    }
                    uint32_t vh = 0u, vl = 0u;
                    if (ok) { vh = __ldg(sH + poff); vl = __ldg(sL + poff); }
                    bH[p] = vh;
                    bL[p] = vl;
                }
            }
        }

        if (c > 0) {
            const int buf = (c - 1) & 1;
            const uint32_t* asH = sm + buf * 5120;
            const uint32_t* asL = sm + 10240 + buf * 5120;
            const uint32_t* bsH = sm + 20480 + buf * 2560;
            const uint32_t* bsL = sm + 25600 + buf * 2560;

#pragma unroll
            for (int kk = 0; kk < 2; kk++) {
                uint32_t aH[2][4], aL[2][4];
#pragma unroll
                for (int ma = 0; ma < 2; ma++) {
                    const int row = wid8 * 32 + 16 * ma + g;
                    uint2 p  = *(const uint2*)(asH + row * 20 + 8 * kk + 2 * t4);
                    uint2 q  = *(const uint2*)(asH + (row + 8) * 20 + 8 * kk + 2 * t4);
                    aH[ma][0] = p.x;  aH[ma][1] = q.x;
                    aH[ma][2] = p.y;  aH[ma][3] = q.y;
                    uint2 pl = *(const uint2*)(asL + row * 20 + 8 * kk + 2 * t4);
                    uint2 ql = *(const uint2*)(asL + (row + 8) * 20 + 8 * kk + 2 * t4);
                    aL[ma][0] = pl.x; aL[ma][1] = ql.x;
                    aL[ma][2] = pl.y; aL[ma][3] = ql.y;
                }
#pragma unroll
                for (int h = 0; h < 2; h++) {
                    uint32_t bH[4][2], bL[4][2];
#pragma unroll
                    for (int na = 0; na < 4; na++) {
                        const int col = ng * 64 + 8 * (4 * h + na) + g;
                        uint2 pb = *(const uint2*)(bsH + col * 20 + 8 * kk + 2 * t4);
                        bH[na][0] = pb.x; bH[na][1] = pb.y;
                        uint2 qb = *(const uint2*)(bsL + col * 20 + 8 * kk + 2 * t4);
                        bL[na][0] = qb.x; bL[na][1] = qb.y;
                    }
#pragma unroll
                    for (int ma = 0; ma < 2; ma++)
#pragma unroll
                        for (int na = 0; na < 4; na++) {
                            MMA16816(acc[ma][4 * h + na], aH[ma], bH[na]);
                            MMA16816(acc[ma][4 * h + na], aH[ma], bL[na]);
                            MMA16816(acc[ma][4 * h + na], aL[ma], bH[na]);
                        }
                }
            }
        }
        __syncthreads();
    }

    // ---- epilogue: transpose to sep[256][129], fused LSTM, pair-plane out ----
#pragma unroll
    for (int ma = 0; ma < 2; ma++)
#pragma unroll
        for (int na = 0; na < 8; na++) {
            const int row = wid8 * 32 + 16 * ma + g;
            const int col = ng * 64 + 8 * na + 2 * t4;
            sep[row * 129 + col]           = acc[ma][na][0];
            sep[row * 129 + col + 1]       = acc[ma][na][1];
            sep[(row + 8) * 129 + col]     = acc[ma][na][2];
            sep[(row + 8) * 129 + col + 1] = acc[ma][na][3];
        }
    __syncthreads();

#pragma unroll
    for (int j = 0; j < 8; j++) {
        const int item = tid + 512 * j;        // 0..4095 = (ph 0..31, p 0..127)
        const int ph = item >> 7;
        const int p  = item & 127;
        float hv[2];
#pragma unroll
        for (int e = 0; e < 2; e++) {
            const int hid = 2 * ph + e;
            const float iv = sep[hid * 129 + p]         + bias[hid];
            const float fv = sep[(64 + hid) * 129 + p]  + bias[64 + hid];
            const float ov = sep[(128 + hid) * 129 + p] + bias[128 + hid];
            const float gv = sep[(192 + hid) * 129 + p] + bias[192 + hid];
            const size_t idx = (((size_t)b * 64 + hid) << 12) + y0 * 128 + p;
            const float cn = fsig(fv) * C[idx] + fsig(iv) * ftanh(gv);
            C[idx] = cn;
            hv[e] = fsig(ov) * ftanh(cn);
        }
        uint32_t lo;
        uint32_t hi = pack_hl(hv[0], hv[1], lo);
        const size_t op = ((size_t)(b * 32 + ph) << 12) + y0 * 128 + p;
        oH[op] = hi;
        oL[op] = lo;
    }
}

// 1x1 conv head (64 -> 1) + ReLU; reconstructs h1 = hi + lo from pair planes.
__global__ void head_kernel(const uint32_t* __restrict__ h1h,
                            const uint32_t* __restrict__ h1l,
                            const float* __restrict__ wh,
                            const float* __restrict__ bh,
                            float* __restrict__ out)
{
    int idx = blockIdx.x * blockDim.x + threadIdx.x;   // 65536
    int b   = idx >> 12;
    int pix = idx & 4095;
    float s = bh[0];
#pragma unroll
    for (int ph = 0; ph < 32; ph++) {
        const size_t op = ((size_t)(b * 32 + ph) << 12) + pix;
        uint32_t h = h1h[op], l = h1l[op];
        float v0 = bflo(h) + bflo(l);
        float v1 = bfhi(h) + bfhi(l);
        s = fmaf(wh[2 * ph], v0, s);
        s = fmaf(wh[2 * ph + 1], v1, s);
    }
    out[idx] = fmaxf(s, 0.f);
}

// ------------------------------- launch -------------------------------------

extern "C" void kernel_launch(void* const* d_in, const int* in_sizes, int n_in,
                              void* d_out, int out_size)
{
    const float* x  = (const float*)d_in[0];
    const float* w0 = (const float*)d_in[1];
    const float* b0 = (const float*)d_in[2];
    const float* w1 = (const float*)d_in[3];
    const float* b1 = (const float*)d_in[4];
    const float* wh = (const float*)d_in[5];
    const float* bh = (const float*)d_in[6];
    float* out = (float*)d_out;

    float *c0, *c1;
    uint32_t *h0h, *h0l, *h1h, *h1l, *xph, *xpl, *wh0, *wl0, *wh1, *wl1;
    cudaGetSymbolAddress((void**)&c0,  g_c0);
    cudaGetSymbolAddress((void**)&c1,  g_c1);
    cudaGetSymbolAddress((void**)&h0h, g_h0h);
    cudaGetSymbolAddress((void**)&h0l, g_h0l);
    cudaGetSymbolAddress((void**)&h1h, g_h1h);
    cudaGetSymbolAddress((void**)&h1l, g_h1l);
    cudaGetSymbolAddress((void**)&xph, g_xph);
    cudaGetSymbolAddress((void**)&xpl, g_xpl);
    cudaGetSymbolAddress((void**)&wh0, g_wh0);
    cudaGetSymbolAddress((void**)&wl0, g_wl0);
    cudaGetSymbolAddress((void**)&wh1, g_wh1);
    cudaGetSymbolAddress((void**)&wl1, g_wl1);

    cudaFuncSetAttribute(convlstm_mma<0>,
                         cudaFuncAttributeMaxDynamicSharedMemorySize, DYN_SMEM);
    cudaFuncSetAttribute(convlstm_mma<1>,
                         cudaFuncAttributeMaxDynamicSharedMemorySize, DYN_SMEM);

    zero_state_kernel<<<HSZ / 256, 256>>>();
    build_xpairs<<<16 * 16 * 4096 / 256, 256>>>(x);
    build_w0k<<<(NCH0 * 4096 + 255) / 256, 256>>>(w0);
    build_w1k<<<(NCH1 * 4096 + 255) / 256, 256>>>(w1);

    dim3 grid(32, 16);   // (2-row group, batch)
    for (int t = 0; t < 16; t++) {
        const int pr = t & 1, pw = (t + 1) & 1;
        // layer 0: pairs = [h0_prev(32) ; x(1)] per tap
        convlstm_mma<0><<<grid, 512, DYN_SMEM>>>(
            wh0, wl0,
            h0h + (size_t)pr * PLSZ, h0l + (size_t)pr * PLSZ,
            xph + (size_t)t * 16 * 4096, xpl + (size_t)t * 16 * 4096,
            b0, c0,
            h0h + (size_t)pw * PLSZ, h0l + (size_t)pw * PLSZ);
        // layer 1: pairs = [h0_new(32) ; h1_prev(32)] per tap
        convlstm_mma<1><<<grid, 512, DYN_SMEM>>>(
            wh1, wl1,
            h0h + (size_t)pw * PLSZ, h0l + (size_t)pw * PLSZ,
            h1h + (size_t)pr * PLSZ, h1l + (size_t)pr * PLSZ,
            b1, c1,
            h1h + (size_t)pw * PLSZ, h1l + (size_t)pw * PLSZ);
    }
    // final h1 in ping-pong slot 0
    head_kernel<<<65536 / 256, 256>>>(h1h, h1l, wh, bh, out);
}

// round 13
// speedup vs baseline: 1.0371x; 1.0371x over previous
#include <cuda_runtime.h>
#include <cuda_bf16.h>
#include <cstdint>

// ---------------------------------------------------------------------------
// ConvLSTM via mma.sync bf16 (hi/lo split, 3 MMAs ~ fp32 accuracy), sm_103a.
// R13 = R11 shape (256 thr, 64 px/CTA, 2 CTAs/SM) +
//   - pre-permuted weight arrays -> A staging = 4x cp.async.16B / thread / chunk
//   - cp.async 3-stage pipeline (stage c+2 during compute c), zfill boundaries
//   - pitch-12 SMEM rows (16B aligned, conflict-free LDS.64 fragments)
// States stored as pre-split packed bf16x2 channel-pair planes (hi & lo).
// ---------------------------------------------------------------------------

#define HSZ   (16 * 64 * 64 * 64)     // planar float cell state [b][64][4096]
#define PLSZ  (16 * 32 * 4096)        // pair planes [b][32][4096] (u32)

__device__ float    g_c0[HSZ], g_c1[HSZ];
__device__ uint32_t g_h0h[2][PLSZ], g_h0l[2][PLSZ];
__device__ uint32_t g_h1h[2][PLSZ], g_h1l[2][PLSZ];
__device__ uint32_t g_xph[16 * 16 * 4096], g_xpl[16 * 16 * 4096]; // [t][b][px]

// pre-permuted packed weight pairs: [chunk][row 256][pos 8] (u32)
#define NCH0 38
#define NCH1 72
__device__ uint32_t g_wh0[NCH0 * 2048], g_wl0[NCH0 * 2048];
__device__ uint32_t g_wh1[NCH1 * 2048], g_wl1[NCH1 * 2048];

__device__ __forceinline__ float fsig(float x) { return 1.f / (1.f + __expf(-x)); }
__device__ __forceinline__ float ftanh(float x) {
    return 2.f / (1.f + __expf(-2.f * x)) - 1.f;
}

__device__ __forceinline__ uint32_t pack_hl(float v0, float v1, uint32_t& lo) {
    __nv_bfloat16 h0 = __float2bfloat16(v0);
    __nv_bfloat16 h1 = __float2bfloat16(v1);
    float r0 = v0 - __bfloat162float(h0);
    float r1 = v1 - __bfloat162float(h1);
    lo = (uint32_t)__bfloat16_as_ushort(__float2bfloat16(r0))
       | ((uint32_t)__bfloat16_as_ushort(__float2bfloat16(r1)) << 16);
    return (uint32_t)__bfloat16_as_ushort(h0)
         | ((uint32_t)__bfloat16_as_ushort(h1) << 16);
}
__device__ __forceinline__ float bflo(uint32_t u) {
    return __bfloat162float(__ushort_as_bfloat16((unsigned short)(u & 0xffff)));
}
__device__ __forceinline__ float bfhi(uint32_t u) {
    return __bfloat162float(__ushort_as_bfloat16((unsigned short)(u >> 16)));
}

#define MMA16816(Cr, Ar, Br) \
    asm volatile("mma.sync.aligned.m16n8k16.row.col.f32.bf16.bf16.f32 " \
        "{%0,%1,%2,%3}, {%4,%5,%6,%7}, {%8,%9}, {%0,%1,%2,%3};" \
        : "+f"((Cr)[0]), "+f"((Cr)[1]), "+f"((Cr)[2]), "+f"((Cr)[3]) \
        : "r"((Ar)[0]), "r"((Ar)[1]), "r"((Ar)[2]), "r"((Ar)[3]), \
          "r"((Br)[0]), "r"((Br)[1]))

// cp.async helpers (sm_80 baseline -> compiles at compute_103)
__device__ __forceinline__ void cp16(uint32_t dst, const void* src) {
    asm volatile("cp.async.cg.shared.global [%0], [%1], 16;"
                 :: "r"(dst), "l"(src) : "memory");
}
__device__ __forceinline__ void cp4z(uint32_t dst, const void* src, int srcsz) {
    asm volatile("cp.async.ca.shared.global [%0], [%1], 4, %2;"
                 :: "r"(dst), "l"(src), "r"(srcsz) : "memory");
}
__device__ __forceinline__ void cp_commit() {
    asm volatile("cp.async.commit_group;" ::: "memory");
}
template <int N> __device__ __forceinline__ void cp_wait() {
    asm volatile("cp.async.wait_group %0;" :: "n"(N) : "memory");
}

// stored pos p (0..7) -> pair-in-chunk u (k-perm [0,4,1,5,2,6,3,7])
__device__ __forceinline__ int pos2u(int p) {
    return (p >> 1) + ((p & 1) << 2);
}

// ------------------------------ prep kernels --------------------------------

__global__ void zero_state_kernel() {
    int i = blockIdx.x * blockDim.x + threadIdx.x;
    if (i < HSZ) { g_c0[i] = 0.f; g_c1[i] = 0.f; }
    if (i < PLSZ) {
        g_h0h[0][i] = 0u; g_h0l[0][i] = 0u;
        g_h1h[0][i] = 0u; g_h1l[0][i] = 0u;
    }
}

__global__ void build_xpairs(const float* __restrict__ x) {
    int idx = blockIdx.x * blockDim.x + threadIdx.x;   // 16*16*4096
    int t  = idx >> 16;
    int b  = (idx >> 12) & 15;
    int px = idx & 4095;
    float v = x[(((size_t)b * 16 + t) << 12) + px];
    uint32_t lo;
    uint32_t hi = pack_hl(v, 0.f, lo);
    g_xph[idx] = hi;
    g_xpl[idx] = lo;
}

// layer0: gu: kt=gu/33, j=gu%33; j<32 -> ic(1+2j, 2+2j); j==32 -> (x,0)
__global__ void build_w0k(const float* __restrict__ W) {
    int idx = blockIdx.x * blockDim.x + threadIdx.x;   // NCH0*2048
    if (idx >= NCH0 * 2048) return;
    int p  = idx & 7;
    int oc = (idx >> 3) & 255;
    int c  = idx >> 11;
    int gu = c * 8 + pos2u(p);
    float v0 = 0.f, v1 = 0.f;
    if (gu < 297) {
        int kt = gu / 33, j = gu - kt * 33;
        if (j < 32) {
            v0 = W[((size_t)oc * 65 + (1 + 2 * j)) * 9 + kt];
            v1 = W[((size_t)oc * 65 + (2 + 2 * j)) * 9 + kt];
        } else {
            v0 = W[((size_t)oc * 65 + 0) * 9 + kt];
        }
    }
    uint32_t lo;
    uint32_t hi = pack_hl(v0, v1, lo);
    g_wh0[idx] = hi;
    g_wl0[idx] = lo;
}

// layer1: gu: kt=gu>>6, j=gu&63 -> ic (2j, 2j+1)
__global__ void build_w1k(const float* __restrict__ W) {
    int idx = blockIdx.x * blockDim.x + threadIdx.x;   // NCH1*2048
    if (idx >= NCH1 * 2048) return;
    int p  = idx & 7;
    int oc = (idx >> 3) & 255;
    int c  = idx >> 11;
    int gu = c * 8 + pos2u(p);
    int kt = gu >> 6, j = gu & 63;
    float v0 = W[((size_t)oc * 128 + 2 * j) * 9 + kt];
    float v1 = W[((size_t)oc * 128 + 2 * j + 1) * 9 + kt];
    uint32_t lo;
    uint32_t hi = pack_hl(v0, v1, lo);
    g_wh1[idx] = hi;
    g_wl1[idx] = lo;
}

// ------------------------------ main kernel ---------------------------------
// SMEM (u32 units), pitch 12 (48B, 16B-aligned rows), 3 buffers:
//   A_H(buf) @ buf*3072        A_L(buf) @ 9216  + buf*3072   (256 rows)
//   B_H(buf) @ 18432 + buf*768 B_L(buf) @ 20736 + buf*768    (64 px)
// Total 23040 u32 = 92160 B.  Epilogue float sep[256][65] (66560 B) unions.
#define DYN_SMEM 92160

template <int LAYER>
__global__ void __launch_bounds__(256, 2)
convlstm_mma(const uint32_t* __restrict__ Wh, const uint32_t* __restrict__ Wl,
             const uint32_t* __restrict__ pAh, const uint32_t* __restrict__ pAl,
             const uint32_t* __restrict__ pBh, const uint32_t* __restrict__ pBl,
             const float* __restrict__ bias,
             float* __restrict__ C,
             uint32_t* __restrict__ oH, uint32_t* __restrict__ oL)
{
    constexpr int PPT = (LAYER == 0) ? 33 : 64;    // pairs per tap
    constexpr int NCH = (LAYER == 0) ? NCH0 : NCH1;
    extern __shared__ uint32_t sm[];
    float* sep = (float*)sm;
    const uint32_t sb = (uint32_t)__cvta_generic_to_shared(sm);

    const int tid = threadIdx.x;
    const int wid = tid >> 5;
    const int lid = tid & 31;
    const int g   = lid >> 2;
    const int t4  = lid & 3;
    const int b   = blockIdx.y;
    const int y0  = blockIdx.x;

    float acc[2][8][4];
#pragma unroll
    for (int i = 0; i < 2; i++)
#pragma unroll
        for (int j = 0; j < 8; j++)
#pragma unroll
            for (int k = 0; k < 4; k++) acc[i][j][k] = 0.f;

    const int bpx = tid & 63;          // pixel x
    const int bu  = tid >> 6;          // 0..3: handles pos bu, bu+4

    // ---- staging lambda (cp.async only) ----
    auto stage = [&](int c) {
        const int buf = c % 3;
        // A: pre-permuted, 8 contiguous u32 per row -> 2x cp16 per hi/lo
        {
            const uint32_t* srcH = Wh + (size_t)c * 2048 + tid * 8;
            const uint32_t* srcL = Wl + (size_t)c * 2048 + tid * 8;
            const uint32_t dH = sb + (buf * 3072 + tid * 12) * 4;
            const uint32_t dL = sb + (9216 + buf * 3072 + tid * 12) * 4;
            cp16(dH, srcH);
            cp16(dH + 16, srcH + 4);
            cp16(dL, srcL);
            cp16(dL + 16, srcL + 4);
        }
        // B: 2 pos per thread, 4B zfill cp.async from pair planes
        {
            const uint32_t bHa = sb + (18432 + buf * 768 + bpx * 12) * 4;
            const uint32_t bLa = sb + (20736 + buf * 768 + bpx * 12) * 4;
#pragma unroll
            for (int s = 0; s < 2; s++) {
                const int p  = bu + 4 * s;
                const int gu = c * 8 + pos2u(p);
                const int kt = gu / PPT;
                const int j  = gu - kt * PPT;
                const int ky = kt / 3;
                const int kx = kt - ky * 3;
                const int y  = y0 + ky - 1;
                const int x  = bpx + kx - 1;
                const bool ok = ((unsigned)y < 64u) && ((unsigned)x < 64u);
                const int poff = ok ? (y * 64 + x) : 0;
                const int srcsz = ok ? 4 : 0;
                const uint32_t* sH;
                const uint32_t* sL;
                if (j < 32) {
                    sH = pAh + ((size_t)(b * 32 + j) << 12);
                    sL = pAl + ((size_t)(b * 32 + j) << 12);
                } else if (LAYER == 0) {
                    sH = pBh + ((size_t)b << 12);
                    sL = pBl + ((size_t)b << 12);
                } else {
                    sH = pBh + ((size_t)(b * 32 + j - 32) << 12);
                    sL = pBl + ((size_t)(b * 32 + j - 32) << 12);
                }
                cp4z(bHa + p * 4, sH + poff, srcsz);
                cp4z(bLa + p * 4, sL + poff, srcsz);
            }
        }
        cp_commit();
    };

    // ---- 3-stage pipeline ----
    stage(0);
    stage(1);

    for (int c = 0; c < NCH; c++) {
        if (c + 1 < NCH) cp_wait<1>(); else cp_wait<0>();
        __syncthreads();

        const int buf = c % 3;
        const uint32_t* asH = sm + buf * 3072;
        const uint32_t* asL = sm + 9216 + buf * 3072;
        const uint32_t* bsH = sm + 18432 + buf * 768;
        const uint32_t* bsL = sm + 20736 + buf * 768;

        uint32_t aH[2][4], aL[2][4];
#pragma unroll
        for (int ma = 0; ma < 2; ma++) {
            const int row = wid * 32 + 16 * ma + g;
            uint2 p  = *(const uint2*)(asH + row * 12 + 2 * t4);
            uint2 q  = *(const uint2*)(asH + (row + 8) * 12 + 2 * t4);
            aH[ma][0] = p.x;  aH[ma][1] = q.x;
            aH[ma][2] = p.y;  aH[ma][3] = q.y;
            uint2 pl = *(const uint2*)(asL + row * 12 + 2 * t4);
            uint2 ql = *(const uint2*)(asL + (row + 8) * 12 + 2 * t4);
            aL[ma][0] = pl.x; aL[ma][1] = ql.x;
            aL[ma][2] = pl.y; aL[ma][3] = ql.y;
        }
#pragma unroll
        for (int h = 0; h < 2; h++) {
            uint32_t bH[4][2], bL[4][2];
#pragma unroll
            for (int na = 0; na < 4; na++) {
                const int col = 8 * (4 * h + na) + g;
                uint2 pb = *(const uint2*)(bsH + col * 12 + 2 * t4);
                bH[na][0] = pb.x; bH[na][1] = pb.y;
                uint2 qb = *(const uint2*)(bsL + col * 12 + 2 * t4);
                bL[na][0] = qb.x; bL[na][1] = qb.y;
            }
#pragma unroll
            for (int ma = 0; ma < 2; ma++)
#pragma unroll
                for (int na = 0; na < 4; na++) {
                    MMA16816(acc[ma][4 * h + na], aH[ma], bH[na]);
                    MMA16816(acc[ma][4 * h + na], aH[ma], bL[na]);
                    MMA16816(acc[ma][4 * h + na], aL[ma], bH[na]);
                }
        }

        if (c + 2 < NCH) stage(c + 2);
    }
    __syncthreads();   // all warps done reading staging SMEM before sep reuse

    // ---- epilogue: transpose to sep[256][65], fused LSTM, pair-plane out ----
#pragma unroll
    for (int ma = 0; ma < 2; ma++)
#pragma unroll
        for (int na = 0; na < 8; na++) {
            const int row = wid * 32 + 16 * ma + g;
            const int col = 8 * na + 2 * t4;
            sep[row * 65 + col]           = acc[ma][na][0];
            sep[row * 65 + col + 1]       = acc[ma][na][1];
            sep[(row + 8) * 65 + col]     = acc[ma][na][2];
            sep[(row + 8) * 65 + col + 1] = acc[ma][na][3];
        }
    __syncthreads();

#pragma unroll
    for (int j = 0; j < 8; j++) {
        const int item = tid + 256 * j;        // 0..2047 = (ph 0..31, x 0..63)
        const int ph = item >> 6;
        const int x  = item & 63;
        float hv[2];
#pragma unroll
        for (int e = 0; e < 2; e++) {
            const int hid = 2 * ph + e;
            const float iv = sep[hid * 65 + x]         + bias[hid];
            const float fv = sep[(64 + hid) * 65 + x]  + bias[64 + hid];
            const float ov = sep[(128 + hid) * 65 + x] + bias[128 + hid];
            const float gv = sep[(192 + hid) * 65 + x] + bias[192 + hid];
            const size_t idx = (((size_t)b * 64 + hid) << 12) + y0 * 64 + x;
            const float cn = fsig(fv) * C[idx] + fsig(iv) * ftanh(gv);
            C[idx] = cn;
            hv[e] = fsig(ov) * ftanh(cn);
        }
        uint32_t lo;
        uint32_t hi = pack_hl(hv[0], hv[1], lo);
        const size_t op = ((size_t)(b * 32 + ph) << 12) + y0 * 64 + x;
        oH[op] = hi;
        oL[op] = lo;
    }
}

// 1x1 conv head (64 -> 1) + ReLU; reconstructs h1 = hi + lo from pair planes.
__global__ void head_kernel(const uint32_t* __restrict__ h1h,
                            const uint32_t* __restrict__ h1l,
                            const float* __restrict__ wh,
                            const float* __restrict__ bh,
                            float* __restrict__ out)
{
    int idx = blockIdx.x * blockDim.x + threadIdx.x;   // 65536
    int b   = idx >> 12;
    int pix = idx & 4095;
    float s = bh[0];
#pragma unroll
    for (int ph = 0; ph < 32; ph++) {
        const size_t op = ((size_t)(b * 32 + ph) << 12) + pix;
        uint32_t h = h1h[op], l = h1l[op];
        float v0 = bflo(h) + bflo(l);
        float v1 = bfhi(h) + bfhi(l);
        s = fmaf(wh[2 * ph], v0, s);
        s = fmaf(wh[2 * ph + 1], v1, s);
    }
    out[idx] = fmaxf(s, 0.f);
}

// ------------------------------- launch -------------------------------------

extern "C" void kernel_launch(void* const* d_in, const int* in_sizes, int n_in,
                              void* d_out, int out_size)
{
    const float* x  = (const float*)d_in[0];
    const float* w0 = (const float*)d_in[1];
    const float* b0 = (const float*)d_in[2];
    const float* w1 = (const float*)d_in[3];
    const float* b1 = (const float*)d_in[4];
    const float* wh = (const float*)d_in[5];
    const float* bh = (const float*)d_in[6];
    float* out = (float*)d_out;

    float *c0, *c1;
    uint32_t *h0h, *h0l, *h1h, *h1l, *xph, *xpl, *wh0, *wl0, *wh1, *wl1;
    cudaGetSymbolAddress((void**)&c0,  g_c0);
    cudaGetSymbolAddress((void**)&c1,  g_c1);
    cudaGetSymbolAddress((void**)&h0h, g_h0h);
    cudaGetSymbolAddress((void**)&h0l, g_h0l);
    cudaGetSymbolAddress((void**)&h1h, g_h1h);
    cudaGetSymbolAddress((void**)&h1l, g_h1l);
    cudaGetSymbolAddress((void**)&xph, g_xph);
    cudaGetSymbolAddress((void**)&xpl, g_xpl);
    cudaGetSymbolAddress((void**)&wh0, g_wh0);
    cudaGetSymbolAddress((void**)&wl0, g_wl0);
    cudaGetSymbolAddress((void**)&wh1, g_wh1);
    cudaGetSymbolAddress((void**)&wl1, g_wl1);

    cudaFuncSetAttribute(convlstm_mma<0>,
                         cudaFuncAttributeMaxDynamicSharedMemorySize, DYN_SMEM);
    cudaFuncSetAttribute(convlstm_mma<1>,
                         cudaFuncAttributeMaxDynamicSharedMemorySize, DYN_SMEM);

    zero_state_kernel<<<HSZ / 256, 256>>>();
    build_xpairs<<<16 * 16 * 4096 / 256, 256>>>(x);
    build_w0k<<<(NCH0 * 2048 + 255) / 256, 256>>>(w0);
    build_w1k<<<(NCH1 * 2048 + 255) / 256, 256>>>(w1);

    dim3 grid(64, 16);   // (image row, batch)
    for (int t = 0; t < 16; t++) {
        const int pr = t & 1, pw = (t + 1) & 1;
        // layer 0: pairs = [h0_prev(32) ; x(1)] per tap
        convlstm_mma<0><<<grid, 256, DYN_SMEM>>>(
            wh0, wl0,
            h0h + (size_t)pr * PLSZ, h0l + (size_t)pr * PLSZ,
            xph + (size_t)t * 16 * 4096, xpl + (size_t)t * 16 * 4096,
            b0, c0,
            h0h + (size_t)pw * PLSZ, h0l + (size_t)pw * PLSZ);
        // layer 1: pairs = [h0_new(32) ; h1_prev(32)] per tap
        convlstm_mma<1><<<grid, 256, DYN_SMEM>>>(
            wh1, wl1,
            h0h + (size_t)pw * PLSZ, h0l + (size_t)pw * PLSZ,
            h1h + (size_t)pr * PLSZ, h1l + (size_t)pr * PLSZ,
            b1, c1,
            h1h + (size_t)pw * PLSZ, h1l + (size_t)pw * PLSZ);
    }
    // final h1 in ping-pong slot 0
    head_kernel<<<65536 / 256, 256>>>(h1h, h1l, wh, bh, out);
}

// round 14
// speedup vs baseline: 1.1736x; 1.1316x over previous
#include <cuda_runtime.h>
#include <cuda_bf16.h>
#include <cstdint>

// ---------------------------------------------------------------------------
// ConvLSTM via mma.sync bf16 (hi/lo split, 3 MMAs ~ fp32 accuracy), sm_103a.
// R14 = R11 shape (256 thr, 64 px/CTA, 2 CTAs/SM, stage-then-compute + 1 sync)
//   + pre-permuted uint4 weight staging (2xLDG.128+2xSTS.128 per k16 hi/lo)
//   + chunk32 (two k16 groups per sync -> half the barriers)
// States stored as pre-split packed bf16x2 channel-pair planes (hi & lo).
// ---------------------------------------------------------------------------

#define HSZ   (16 * 64 * 64 * 64)     // planar float cell state [b][64][4096]
#define PLSZ  (16 * 32 * 4096)        // pair planes [b][32][4096] (u32)

__device__ float    g_c0[HSZ], g_c1[HSZ];
__device__ uint32_t g_h0h[2][PLSZ], g_h0l[2][PLSZ];
__device__ uint32_t g_h1h[2][PLSZ], g_h1l[2][PLSZ];
__device__ uint32_t g_xph[16 * 16 * 4096], g_xpl[16 * 16 * 4096]; // [t][b][px]

// pre-permuted packed weight pairs: [chunk16][row 256][pos 8] (u32)
#define NCH0 38
#define NCH1 72
#define NC2_0 (NCH0 / 2)   // 19 chunk32s
#define NC2_1 (NCH1 / 2)   // 36 chunk32s
__device__ uint32_t g_wh0[NCH0 * 2048], g_wl0[NCH0 * 2048];
__device__ uint32_t g_wh1[NCH1 * 2048], g_wl1[NCH1 * 2048];

__device__ __forceinline__ float fsig(float x) { return 1.f / (1.f + __expf(-x)); }
__device__ __forceinline__ float ftanh(float x) {
    return 2.f / (1.f + __expf(-2.f * x)) - 1.f;
}

__device__ __forceinline__ uint32_t pack_hl(float v0, float v1, uint32_t& lo) {
    __nv_bfloat16 h0 = __float2bfloat16(v0);
    __nv_bfloat16 h1 = __float2bfloat16(v1);
    float r0 = v0 - __bfloat162float(h0);
    float r1 = v1 - __bfloat162float(h1);
    lo = (uint32_t)__bfloat16_as_ushort(__float2bfloat16(r0))
       | ((uint32_t)__bfloat16_as_ushort(__float2bfloat16(r1)) << 16);
    return (uint32_t)__bfloat16_as_ushort(h0)
         | ((uint32_t)__bfloat16_as_ushort(h1) << 16);
}
__device__ __forceinline__ float bflo(uint32_t u) {
    return __bfloat162float(__ushort_as_bfloat16((unsigned short)(u & 0xffff)));
}
__device__ __forceinline__ float bfhi(uint32_t u) {
    return __bfloat162float(__ushort_as_bfloat16((unsigned short)(u >> 16)));
}

#define MMA16816(Cr, Ar, Br) \
    asm volatile("mma.sync.aligned.m16n8k16.row.col.f32.bf16.bf16.f32 " \
        "{%0,%1,%2,%3}, {%4,%5,%6,%7}, {%8,%9}, {%0,%1,%2,%3};" \
        : "+f"((Cr)[0]), "+f"((Cr)[1]), "+f"((Cr)[2]), "+f"((Cr)[3]) \
        : "r"((Ar)[0]), "r"((Ar)[1]), "r"((Ar)[2]), "r"((Ar)[3]), \
          "r"((Br)[0]), "r"((Br)[1]))

// stored pos p (0..7) -> pair-in-chunk16 u (k-perm [0,4,1,5,2,6,3,7])
__device__ __forceinline__ int pos2u(int p) {
    return (p >> 1) + ((p & 1) << 2);
}

// ------------------------------ prep kernels --------------------------------

__global__ void zero_state_kernel() {
    int i = blockIdx.x * blockDim.x + threadIdx.x;
    if (i < HSZ) { g_c0[i] = 0.f; g_c1[i] = 0.f; }
    if (i < PLSZ) {
        g_h0h[0][i] = 0u; g_h0l[0][i] = 0u;
        g_h1h[0][i] = 0u; g_h1l[0][i] = 0u;
    }
}

__global__ void build_xpairs(const float* __restrict__ x) {
    int idx = blockIdx.x * blockDim.x + threadIdx.x;   // 16*16*4096
    int t  = idx >> 16;
    int b  = (idx >> 12) & 15;
    int px = idx & 4095;
    float v = x[(((size_t)b * 16 + t) << 12) + px];
    uint32_t lo;
    uint32_t hi = pack_hl(v, 0.f, lo);
    g_xph[idx] = hi;
    g_xpl[idx] = lo;
}

// layer0: gu: kt=gu/33, j=gu%33; j<32 -> ic(1+2j, 2+2j); j==32 -> (x,0)
__global__ void build_w0k(const float* __restrict__ W) {
    int idx = blockIdx.x * blockDim.x + threadIdx.x;   // NCH0*2048
    if (idx >= NCH0 * 2048) return;
    int p  = idx & 7;
    int oc = (idx >> 3) & 255;
    int c  = idx >> 11;
    int gu = c * 8 + pos2u(p);
    float v0 = 0.f, v1 = 0.f;
    if (gu < 297) {
        int kt = gu / 33, j = gu - kt * 33;
        if (j < 32) {
            v0 = W[((size_t)oc * 65 + (1 + 2 * j)) * 9 + kt];
            v1 = W[((size_t)oc * 65 + (2 + 2 * j)) * 9 + kt];
        } else {
            v0 = W[((size_t)oc * 65 + 0) * 9 + kt];
        }
    }
    uint32_t lo;
    uint32_t hi = pack_hl(v0, v1, lo);
    g_wh0[idx] = hi;
    g_wl0[idx] = lo;
}

// layer1: gu: kt=gu>>6, j=gu&63 -> ic (2j, 2j+1)
__global__ void build_w1k(const float* __restrict__ W) {
    int idx = blockIdx.x * blockDim.x + threadIdx.x;   // NCH1*2048
    if (idx >= NCH1 * 2048) return;
    int p  = idx & 7;
    int oc = (idx >> 3) & 255;
    int c  = idx >> 11;
    int gu = c * 8 + pos2u(p);
    int kt = gu >> 6, j = gu & 63;
    float v0 = W[((size_t)oc * 128 + 2 * j) * 9 + kt];
    float v1 = W[((size_t)oc * 128 + 2 * j + 1) * 9 + kt];
    uint32_t lo;
    uint32_t hi = pack_hl(v0, v1, lo);
    g_wh1[idx] = hi;
    g_wl1[idx] = lo;
}

// ------------------------------ main kernel ---------------------------------
// SMEM (u32 units), double-buffered chunk32:
//   A_H @ buf*5120 (256 rows x pitch 20, 16 data u32)      total 10240
//   A_L @ 10240 + buf*5120                                 total 20480
//   B_H @ 20480 + buf*1152 (64 px x pitch 18, 16 data)     total 22784
//   B_L @ 22784 + buf*1152                                 total 25088
// = 100352 B.  Epilogue float sep[256][65] (66560 B) unions over it.
#define DYN_SMEM 100352

template <int LAYER>
__global__ void __launch_bounds__(256, 2)
convlstm_mma(const uint32_t* __restrict__ Wh, const uint32_t* __restrict__ Wl,
             const uint32_t* __restrict__ pAh, const uint32_t* __restrict__ pAl,
             const uint32_t* __restrict__ pBh, const uint32_t* __restrict__ pBl,
             const float* __restrict__ bias,
             float* __restrict__ C,
             uint32_t* __restrict__ oH, uint32_t* __restrict__ oL)
{
    constexpr int PPT = (LAYER == 0) ? 33 : 64;      // pairs per tap
    constexpr int NC2 = (LAYER == 0) ? NC2_0 : NC2_1;
    extern __shared__ uint32_t sm[];
    float* sep = (float*)sm;

    const int tid = threadIdx.x;
    const int wid = tid >> 5;
    const int lid = tid & 31;
    const int g   = lid >> 2;
    const int t4  = lid & 3;
    const int b   = blockIdx.y;
    const int y0  = blockIdx.x;

    float acc[2][8][4];
#pragma unroll
    for (int i = 0; i < 2; i++)
#pragma unroll
        for (int j = 0; j < 8; j++)
#pragma unroll
            for (int k = 0; k < 4; k++) acc[i][j][k] = 0.f;

    const int bpx = tid & 63;          // pixel x for B staging
    const int bu  = tid >> 6;          // 0..3: handles pos bu+4s, s=0..3

    for (int c2 = 0; c2 < NC2 + 1; c2++) {
        // ---- stage chunk32 c2 into buf c2&1 ----
        if (c2 < NC2) {
            const int buf = c2 & 1;
            // A: pre-permuted weights, uint4 moves
            {
                const uint4* s0H = (const uint4*)(Wh + (size_t)(2 * c2) * 2048) + tid * 2;
                const uint4* s1H = (const uint4*)(Wh + (size_t)(2 * c2 + 1) * 2048) + tid * 2;
                const uint4* s0L = (const uint4*)(Wl + (size_t)(2 * c2) * 2048) + tid * 2;
                const uint4* s1L = (const uint4*)(Wl + (size_t)(2 * c2 + 1) * 2048) + tid * 2;
                uint4 h0 = s0H[0], h1 = s0H[1], h2 = s1H[0], h3 = s1H[1];
                uint4 l0 = s0L[0], l1 = s0L[1], l2 = s1L[0], l3 = s1L[1];
                uint32_t* dH = sm + buf * 5120 + tid * 20;
                uint32_t* dL = sm + 10240 + buf * 5120 + tid * 20;
                ((uint4*)dH)[0] = h0; ((uint4*)dH)[1] = h1;
                ((uint4*)(dH + 8))[0] = h2; ((uint4*)(dH + 8))[1] = h3;
                ((uint4*)dL)[0] = l0; ((uint4*)dL)[1] = l1;
                ((uint4*)(dL + 8))[0] = l2; ((uint4*)(dL + 8))[1] = l3;
            }
            // B: predicated scalar LDG.32 from pair planes
            {
                uint32_t* bH = sm + 20480 + buf * 1152 + bpx * 18;
                uint32_t* bL = sm + 22784 + buf * 1152 + bpx * 18;
#pragma unroll
                for (int s = 0; s < 4; s++) {
                    const int pos = bu + 4 * s;          // 0..15
                    const int kk  = pos >> 3;
                    const int gu  = (2 * c2 + kk) * 8 + pos2u(pos & 7);
                    const int kt  = gu / PPT;
                    const int j   = gu - kt * PPT;
                    const int ky  = kt / 3;
                    const int kx  = kt - ky * 3;
                    const int y   = y0 + ky - 1;
                    const int x   = bpx + kx - 1;
                    const bool ok = ((unsigned)y < 64u) && ((unsigned)x < 64u);
                    const int poff = y * 64 + x;
                    const uint32_t* sH;
                    const uint32_t* sL;
                    if (j < 32) {
                        sH = pAh + ((size_t)(b * 32 + j) << 12);
                        sL = pAl + ((size_t)(b * 32 + j) << 12);
                    } else if (LAYER == 0) {
                        sH = pBh + ((size_t)b << 12);
                        sL = pBl + ((size_t)b << 12);
                    } else {
                        sH = pBh + ((size_t)(b * 32 + j - 32) << 12);
                        sL = pBl + ((size_t)(b * 32 + j - 32) << 12);
                    }
                    uint32_t vh = 0u, vl = 0u;
                    if (ok) { vh = __ldg(sH + poff); vl = __ldg(sL + poff); }
                    bH[pos] = vh;
                    bL[pos] = vl;
                }
            }
        }

        // ---- compute chunk32 c2-1 from buf (c2-1)&1 ----
        if (c2 > 0) {
            const int buf = (c2 - 1) & 1;
            const uint32_t* asH = sm + buf * 5120;
            const uint32_t* asL = sm + 10240 + buf * 5120;
            const uint32_t* bsH = sm + 20480 + buf * 1152;
            const uint32_t* bsL = sm + 22784 + buf * 1152;

#pragma unroll
            for (int kk = 0; kk < 2; kk++) {
                uint32_t aH[2][4], aL[2][4];
#pragma unroll
                for (int ma = 0; ma < 2; ma++) {
                    const int row = wid * 32 + 16 * ma + g;
                    uint2 p  = *(const uint2*)(asH + row * 20 + 8 * kk + 2 * t4);
                    uint2 q  = *(const uint2*)(asH + (row + 8) * 20 + 8 * kk + 2 * t4);
                    aH[ma][0] = p.x;  aH[ma][1] = q.x;
                    aH[ma][2] = p.y;  aH[ma][3] = q.y;
                    uint2 pl = *(const uint2*)(asL + row * 20 + 8 * kk + 2 * t4);
                    uint2 ql = *(const uint2*)(asL + (row + 8) * 20 + 8 * kk + 2 * t4);
                    aL[ma][0] = pl.x; aL[ma][1] = ql.x;
                    aL[ma][2] = pl.y; aL[ma][3] = ql.y;
                }
#pragma unroll
                for (int h = 0; h < 2; h++) {
                    uint32_t bH[4][2], bL[4][2];
#pragma unroll
                    for (int na = 0; na < 4; na++) {
                        const int col = 8 * (4 * h + na) + g;
                        uint2 pb = *(const uint2*)(bsH + col * 18 + 8 * kk + 2 * t4);
                        bH[na][0] = pb.x; bH[na][1] = pb.y;
                        uint2 qb = *(const uint2*)(bsL + col * 18 + 8 * kk + 2 * t4);
                        bL[na][0] = qb.x; bL[na][1] = qb.y;
                    }
#pragma unroll
                    for (int ma = 0; ma < 2; ma++)
#pragma unroll
                        for (int na = 0; na < 4; na++) {
                            MMA16816(acc[ma][4 * h + na], aH[ma], bH[na]);
                            MMA16816(acc[ma][4 * h + na], aH[ma], bL[na]);
                            MMA16816(acc[ma][4 * h + na], aL[ma], bH[na]);
                        }
                }
            }
        }
        __syncthreads();
    }

    // ---- epilogue: transpose to sep[256][65], fused LSTM, pair-plane out ----
#pragma unroll
    for (int ma = 0; ma < 2; ma++)
#pragma unroll
        for (int na = 0; na < 8; na++) {
            const int row = wid * 32 + 16 * ma + g;
            const int col = 8 * na + 2 * t4;
            sep[row * 65 + col]           = acc[ma][na][0];
            sep[row * 65 + col + 1]       = acc[ma][na][1];
            sep[(row + 8) * 65 + col]     = acc[ma][na][2];
            sep[(row + 8) * 65 + col + 1] = acc[ma][na][3];
        }
    __syncthreads();

#pragma unroll
    for (int j = 0; j < 8; j++) {
        const int item = tid + 256 * j;        // 0..2047 = (ph 0..31, x 0..63)
        const int ph = item >> 6;
        const int x  = item & 63;
        float hv[2];
#pragma unroll
        for (int e = 0; e < 2; e++) {
            const int hid = 2 * ph + e;
            const float iv = sep[hid * 65 + x]         + bias[hid];
            const float fv = sep[(64 + hid) * 65 + x]  + bias[64 + hid];
            const float ov = sep[(128 + hid) * 65 + x] + bias[128 + hid];
            const float gv = sep[(192 + hid) * 65 + x] + bias[192 + hid];
            const size_t idx = (((size_t)b * 64 + hid) << 12) + y0 * 64 + x;
            const float cn = fsig(fv) * C[idx] + fsig(iv) * ftanh(gv);
            C[idx] = cn;
            hv[e] = fsig(ov) * ftanh(cn);
        }
        uint32_t lo;
        uint32_t hi = pack_hl(hv[0], hv[1], lo);
        const size_t op = ((size_t)(b * 32 + ph) << 12) + y0 * 64 + x;
        oH[op] = hi;
        oL[op] = lo;
    }
}

// 1x1 conv head (64 -> 1) + ReLU; reconstructs h1 = hi + lo from pair planes.
__global__ void head_kernel(const uint32_t* __restrict__ h1h,
                            const uint32_t* __restrict__ h1l,
                            const float* __restrict__ wh,
                            const float* __restrict__ bh,
                            float* __restrict__ out)
{
    int idx = blockIdx.x * blockDim.x + threadIdx.x;   // 65536
    int b   = idx >> 12;
    int pix = idx & 4095;
    float s = bh[0];
#pragma unroll
    for (int ph = 0; ph < 32; ph++) {
        const size_t op = ((size_t)(b * 32 + ph) << 12) + pix;
        uint32_t h = h1h[op], l = h1l[op];
        float v0 = bflo(h) + bflo(l);
        float v1 = bfhi(h) + bfhi(l);
        s = fmaf(wh[2 * ph], v0, s);
        s = fmaf(wh[2 * ph + 1], v1, s);
    }
    out[idx] = fmaxf(s, 0.f);
}

// ------------------------------- launch -------------------------------------

extern "C" void kernel_launch(void* const* d_in, const int* in_sizes, int n_in,
                              void* d_out, int out_size)
{
    const float* x  = (const float*)d_in[0];
    const float* w0 = (const float*)d_in[1];
    const float* b0 = (const float*)d_in[2];
    const float* w1 = (const float*)d_in[3];
    const float* b1 = (const float*)d_in[4];
    const float* wh = (const float*)d_in[5];
    const float* bh = (const float*)d_in[6];
    float* out = (float*)d_out;

    float *c0, *c1;
    uint32_t *h0h, *h0l, *h1h, *h1l, *xph, *xpl, *wh0, *wl0, *wh1, *wl1;
    cudaGetSymbolAddress((void**)&c0,  g_c0);
    cudaGetSymbolAddress((void**)&c1,  g_c1);
    cudaGetSymbolAddress((void**)&h0h, g_h0h);
    cudaGetSymbolAddress((void**)&h0l, g_h0l);
    cudaGetSymbolAddress((void**)&h1h, g_h1h);
    cudaGetSymbolAddress((void**)&h1l, g_h1l);
    cudaGetSymbolAddress((void**)&xph, g_xph);
    cudaGetSymbolAddress((void**)&xpl, g_xpl);
    cudaGetSymbolAddress((void**)&wh0, g_wh0);
    cudaGetSymbolAddress((void**)&wl0, g_wl0);
    cudaGetSymbolAddress((void**)&wh1, g_wh1);
    cudaGetSymbolAddress((void**)&wl1, g_wl1);

    cudaFuncSetAttribute(convlstm_mma<0>,
                         cudaFuncAttributeMaxDynamicSharedMemorySize, DYN_SMEM);
    cudaFuncSetAttribute(convlstm_mma<1>,
                         cudaFuncAttributeMaxDynamicSharedMemorySize, DYN_SMEM);

    zero_state_kernel<<<HSZ / 256, 256>>>();
    build_xpairs<<<16 * 16 * 4096 / 256, 256>>>(x);
    build_w0k<<<(NCH0 * 2048 + 255) / 256, 256>>>(w0);
    build_w1k<<<(NCH1 * 2048 + 255) / 256, 256>>>(w1);

    dim3 grid(64, 16);   // (image row, batch)
    for (int t = 0; t < 16; t++) {
        const int pr = t & 1, pw = (t + 1) & 1;
        // layer 0: pairs = [h0_prev(32) ; x(1)] per tap
        convlstm_mma<0><<<grid, 256, DYN_SMEM>>>(
            wh0, wl0,
            h0h + (size_t)pr * PLSZ, h0l + (size_t)pr * PLSZ,
            xph + (size_t)t * 16 * 4096, xpl + (size_t)t * 16 * 4096,
            b0, c0,
            h0h + (size_t)pw * PLSZ, h0l + (size_t)pw * PLSZ);
        // layer 1: pairs = [h0_new(32) ; h1_prev(32)] per tap
        convlstm_mma<1><<<grid, 256, DYN_SMEM>>>(
            wh1, wl1,
            h0h + (size_t)pw * PLSZ, h0l + (size_t)pw * PLSZ,
            h1h + (size_t)pr * PLSZ, h1l + (size_t)pr * PLSZ,
            b1, c1,
            h1h + (size_t)pw * PLSZ, h1l + (size_t)pw * PLSZ);
    }
    // final h1 in ping-pong slot 0
    head_kernel<<<65536 / 256, 256>>>(h1h, h1l, wh, bh, out);
}

// round 15
// speedup vs baseline: 1.3246x; 1.1287x over previous
#include <cuda_runtime.h>
#include <cuda_bf16.h>
#include <cstdint>

// ---------------------------------------------------------------------------
// ConvLSTM via mma.sync bf16 (hi/lo split, 3 MMAs ~ fp32 accuracy), sm_103a.
// R15 = R11 shape (256 thr, 64 px/CTA, 2 CTAs/SM, chunk16) with a REGISTER-
// STAGED PIPELINE: LDG for chunk c+1 issues before compute of chunk c, and the
// dependent STS runs after compute -> the global-load latency is hidden by MMA
// work instead of being exposed at every chunk boundary.
// Pre-permuted uint4 weight arrays (from R14). States as pre-split packed
// bf16x2 channel-pair planes (hi & lo).
// ---------------------------------------------------------------------------

#define HSZ   (16 * 64 * 64 * 64)     // planar float cell state [b][64][4096]
#define PLSZ  (16 * 32 * 4096)        // pair planes [b][32][4096] (u32)

__device__ float    g_c0[HSZ], g_c1[HSZ];
__device__ uint32_t g_h0h[2][PLSZ], g_h0l[2][PLSZ];
__device__ uint32_t g_h1h[2][PLSZ], g_h1l[2][PLSZ];
__device__ uint32_t g_xph[16 * 16 * 4096], g_xpl[16 * 16 * 4096]; // [t][b][px]

// pre-permuted packed weight pairs: [chunk16][row 256][pos 8] (u32)
#define NCH0 38
#define NCH1 72
__device__ uint32_t g_wh0[NCH0 * 2048], g_wl0[NCH0 * 2048];
__device__ uint32_t g_wh1[NCH1 * 2048], g_wl1[NCH1 * 2048];

__device__ __forceinline__ float fsig(float x) { return 1.f / (1.f + __expf(-x)); }
__device__ __forceinline__ float ftanh(float x) {
    return 2.f / (1.f + __expf(-2.f * x)) - 1.f;
}

__device__ __forceinline__ uint32_t pack_hl(float v0, float v1, uint32_t& lo) {
    __nv_bfloat16 h0 = __float2bfloat16(v0);
    __nv_bfloat16 h1 = __float2bfloat16(v1);
    float r0 = v0 - __bfloat162float(h0);
    float r1 = v1 - __bfloat162float(h1);
    lo = (uint32_t)__bfloat16_as_ushort(__float2bfloat16(r0))
       | ((uint32_t)__bfloat16_as_ushort(__float2bfloat16(r1)) << 16);
    return (uint32_t)__bfloat16_as_ushort(h0)
         | ((uint32_t)__bfloat16_as_ushort(h1) << 16);
}
__device__ __forceinline__ float bflo(uint32_t u) {
    return __bfloat162float(__ushort_as_bfloat16((unsigned short)(u & 0xffff)));
}
__device__ __forceinline__ float bfhi(uint32_t u) {
    return __bfloat162float(__ushort_as_bfloat16((unsigned short)(u >> 16)));
}

#define MMA16816(Cr, Ar, Br) \
    asm volatile("mma.sync.aligned.m16n8k16.row.col.f32.bf16.bf16.f32 " \
        "{%0,%1,%2,%3}, {%4,%5,%6,%7}, {%8,%9}, {%0,%1,%2,%3};" \
        : "+f"((Cr)[0]), "+f"((Cr)[1]), "+f"((Cr)[2]), "+f"((Cr)[3]) \
        : "r"((Ar)[0]), "r"((Ar)[1]), "r"((Ar)[2]), "r"((Ar)[3]), \
          "r"((Br)[0]), "r"((Br)[1]))

// stored pos p (0..7) -> pair-in-chunk16 u (k-perm [0,4,1,5,2,6,3,7])
__device__ __forceinline__ int pos2u(int p) {
    return (p >> 1) + ((p & 1) << 2);
}

// ------------------------------ prep kernels --------------------------------

__global__ void zero_state_kernel() {
    int i = blockIdx.x * blockDim.x + threadIdx.x;
    if (i < HSZ) { g_c0[i] = 0.f; g_c1[i] = 0.f; }
    if (i < PLSZ) {
        g_h0h[0][i] = 0u; g_h0l[0][i] = 0u;
        g_h1h[0][i] = 0u; g_h1l[0][i] = 0u;
    }
}

__global__ void build_xpairs(const float* __restrict__ x) {
    int idx = blockIdx.x * blockDim.x + threadIdx.x;   // 16*16*4096
    int t  = idx >> 16;
    int b  = (idx >> 12) & 15;
    int px = idx & 4095;
    float v = x[(((size_t)b * 16 + t) << 12) + px];
    uint32_t lo;
    uint32_t hi = pack_hl(v, 0.f, lo);
    g_xph[idx] = hi;
    g_xpl[idx] = lo;
}

// layer0: gu: kt=gu/33, j=gu%33; j<32 -> ic(1+2j, 2+2j); j==32 -> (x,0)
__global__ void build_w0k(const float* __restrict__ W) {
    int idx = blockIdx.x * blockDim.x + threadIdx.x;   // NCH0*2048
    if (idx >= NCH0 * 2048) return;
    int p  = idx & 7;
    int oc = (idx >> 3) & 255;
    int c  = idx >> 11;
    int gu = c * 8 + pos2u(p);
    float v0 = 0.f, v1 = 0.f;
    if (gu < 297) {
        int kt = gu / 33, j = gu - kt * 33;
        if (j < 32) {
            v0 = W[((size_t)oc * 65 + (1 + 2 * j)) * 9 + kt];
            v1 = W[((size_t)oc * 65 + (2 + 2 * j)) * 9 + kt];
        } else {
            v0 = W[((size_t)oc * 65 + 0) * 9 + kt];
        }
    }
    uint32_t lo;
    uint32_t hi = pack_hl(v0, v1, lo);
    g_wh0[idx] = hi;
    g_wl0[idx] = lo;
}

// layer1: gu: kt=gu>>6, j=gu&63 -> ic (2j, 2j+1)
__global__ void build_w1k(const float* __restrict__ W) {
    int idx = blockIdx.x * blockDim.x + threadIdx.x;   // NCH1*2048
    if (idx >= NCH1 * 2048) return;
    int p  = idx & 7;
    int oc = (idx >> 3) & 255;
    int c  = idx >> 11;
    int gu = c * 8 + pos2u(p);
    int kt = gu >> 6, j = gu & 63;
    float v0 = W[((size_t)oc * 128 + 2 * j) * 9 + kt];
    float v1 = W[((size_t)oc * 128 + 2 * j + 1) * 9 + kt];
    uint32_t lo;
    uint32_t hi = pack_hl(v0, v1, lo);
    g_wh1[idx] = hi;
    g_wl1[idx] = lo;
}

// ------------------------------ main kernel ---------------------------------
// SMEM (u32 units), pitch 12 (48B rows, 16B-aligned), chunk16 double buffer:
//   A_H @ buf*3072 (256 rows)     A_L @ 6144 + buf*3072
//   B_H @ 12288 + buf*768 (64 px) B_L @ 13824 + buf*768
// total 15360 u32 = 61440 B; epilogue float sep[256][65] = 66560 B unions.
#define DYN_SMEM 66560

template <int LAYER>
__global__ void __launch_bounds__(256, 2)
convlstm_mma(const uint32_t* __restrict__ Wh, const uint32_t* __restrict__ Wl,
             const uint32_t* __restrict__ pAh, const uint32_t* __restrict__ pAl,
             const uint32_t* __restrict__ pBh, const uint32_t* __restrict__ pBl,
             const float* __restrict__ bias,
             float* __restrict__ C,
             uint32_t* __restrict__ oH, uint32_t* __restrict__ oL)
{
    constexpr int PPT = (LAYER == 0) ? 33 : 64;      // pairs per tap
    constexpr int NCH = (LAYER == 0) ? NCH0 : NCH1;
    extern __shared__ uint32_t sm[];
    float* sep = (float*)sm;

    const int tid = threadIdx.x;
    const int wid = tid >> 5;
    const int lid = tid & 31;
    const int g   = lid >> 2;
    const int t4  = lid & 3;
    const int b   = blockIdx.y;
    const int y0  = blockIdx.x;

    float acc[2][8][4];
#pragma unroll
    for (int i = 0; i < 2; i++)
#pragma unroll
        for (int j = 0; j < 8; j++)
#pragma unroll
            for (int k = 0; k < 4; k++) acc[i][j][k] = 0.f;

    const int bpx = tid & 63;          // pixel x for B staging
    const int bu  = tid >> 6;          // 0..3: handles pos bu, bu+4

    // ---- pipeline registers ----
    uint4 pah0, pah1, pal0, pal1;      // A chunk prefetch (hi: 8 u32, lo: 8 u32)
    uint32_t pbh[2], pbl[2];           // B chunk prefetch

    // issue LDGs for chunk c into the pipeline registers
    auto ldg_stage = [&](int c) {
        const uint4* sH = (const uint4*)(Wh + (size_t)c * 2048) + tid * 2;
        const uint4* sL = (const uint4*)(Wl + (size_t)c * 2048) + tid * 2;
        pah0 = sH[0]; pah1 = sH[1];
        pal0 = sL[0]; pal1 = sL[1];
#pragma unroll
        for (int s = 0; s < 2; s++) {
            const int pos = bu + 4 * s;
            const int gu  = c * 8 + pos2u(pos);
            const int kt  = gu / PPT;
            const int j   = gu - kt * PPT;
            const int ky  = kt / 3;
            const int kx  = kt - ky * 3;
            const int y   = y0 + ky - 1;
            const int x   = bpx + kx - 1;
            const bool ok = ((unsigned)y < 64u) && ((unsigned)x < 64u);
            const int poff = y * 64 + x;
            const uint32_t* sBh;
            const uint32_t* sBl;
            if (j < 32) {
                sBh = pAh + ((size_t)(b * 32 + j) << 12);
                sBl = pAl + ((size_t)(b * 32 + j) << 12);
            } else if (LAYER == 0) {
                sBh = pBh + ((size_t)b << 12);
                sBl = pBl + ((size_t)b << 12);
            } else {
                sBh = pBh + ((size_t)(b * 32 + j - 32) << 12);
                sBl = pBl + ((size_t)(b * 32 + j - 32) << 12);
            }
            uint32_t vh = 0u, vl = 0u;
            if (ok) { vh = __ldg(sBh + poff); vl = __ldg(sBl + poff); }
            pbh[s] = vh;
            pbl[s] = vl;
        }
    };

    // store the pipeline registers into SMEM buffer `buf`
    auto sts_stage = [&](int buf) {
        uint32_t* dH = sm + buf * 3072 + tid * 12;
        uint32_t* dL = sm + 6144 + buf * 3072 + tid * 12;
        ((uint4*)dH)[0] = pah0; ((uint4*)dH)[1] = pah1;
        ((uint4*)dL)[0] = pal0; ((uint4*)dL)[1] = pal1;
        uint32_t* bH = sm + 12288 + buf * 768 + bpx * 12;
        uint32_t* bL = sm + 13824 + buf * 768 + bpx * 12;
        bH[bu]     = pbh[0];
        bH[bu + 4] = pbh[1];
        bL[bu]     = pbl[0];
        bL[bu + 4] = pbl[1];
    };

    // ---- prologue ----
    ldg_stage(0);
    sts_stage(0);
    __syncthreads();

    // ---- main loop: LDG(c+1) early, compute(c), STS(c+1), sync ----
    for (int c = 0; c < NCH; c++) {
        if (c + 1 < NCH) ldg_stage(c + 1);

        const int buf = c & 1;
        const uint32_t* asH = sm + buf * 3072;
        const uint32_t* asL = sm + 6144 + buf * 3072;
        const uint32_t* bsH = sm + 12288 + buf * 768;
        const uint32_t* bsL = sm + 13824 + buf * 768;

        uint32_t aH[2][4], aL[2][4];
#pragma unroll
        for (int ma = 0; ma < 2; ma++) {
            const int row = wid * 32 + 16 * ma + g;
            uint2 p  = *(const uint2*)(asH + row * 12 + 2 * t4);
            uint2 q  = *(const uint2*)(asH + (row + 8) * 12 + 2 * t4);
            aH[ma][0] = p.x;  aH[ma][1] = q.x;
            aH[ma][2] = p.y;  aH[ma][3] = q.y;
            uint2 pl = *(const uint2*)(asL + row * 12 + 2 * t4);
            uint2 ql = *(const uint2*)(asL + (row + 8) * 12 + 2 * t4);
            aL[ma][0] = pl.x; aL[ma][1] = ql.x;
            aL[ma][2] = pl.y; aL[ma][3] = ql.y;
        }
#pragma unroll
        for (int h = 0; h < 2; h++) {
            uint32_t bH[4][2], bL[4][2];
#pragma unroll
            for (int na = 0; na < 4; na++) {
                const int col = 8 * (4 * h + na) + g;
                uint2 pb = *(const uint2*)(bsH + col * 12 + 2 * t4);
                bH[na][0] = pb.x; bH[na][1] = pb.y;
                uint2 qb = *(const uint2*)(bsL + col * 12 + 2 * t4);
                bL[na][0] = qb.x; bL[na][1] = qb.y;
            }
#pragma unroll
            for (int ma = 0; ma < 2; ma++)
#pragma unroll
                for (int na = 0; na < 4; na++) {
                    MMA16816(acc[ma][4 * h + na], aH[ma], bH[na]);
                    MMA16816(acc[ma][4 * h + na], aH[ma], bL[na]);
                    MMA16816(acc[ma][4 * h + na], aL[ma], bH[na]);
                }
        }

        if (c + 1 < NCH) sts_stage((c + 1) & 1);
        __syncthreads();
    }

    // ---- epilogue: transpose to sep[256][65], fused LSTM, pair-plane out ----
#pragma unroll
    for (int ma = 0; ma < 2; ma++)
#pragma unroll
        for (int na = 0; na < 8; na++) {
            const int row = wid * 32 + 16 * ma + g;
            const int col = 8 * na + 2 * t4;
            sep[row * 65 + col]           = acc[ma][na][0];
            sep[row * 65 + col + 1]       = acc[ma][na][1];
            sep[(row + 8) * 65 + col]     = acc[ma][na][2];
            sep[(row + 8) * 65 + col + 1] = acc[ma][na][3];
        }
    __syncthreads();

#pragma unroll
    for (int j = 0; j < 8; j++) {
        const int item = tid + 256 * j;        // 0..2047 = (ph 0..31, x 0..63)
        const int ph = item >> 6;
        const int x  = item & 63;
        float hv[2];
#pragma unroll
        for (int e = 0; e < 2; e++) {
            const int hid = 2 * ph + e;
            const float iv = sep[hid * 65 + x]         + bias[hid];
            const float fv = sep[(64 + hid) * 65 + x]  + bias[64 + hid];
            const float ov = sep[(128 + hid) * 65 + x] + bias[128 + hid];
            const float gv = sep[(192 + hid) * 65 + x] + bias[192 + hid];
            const size_t idx = (((size_t)b * 64 + hid) << 12) + y0 * 64 + x;
            const float cn = fsig(fv) * C[idx] + fsig(iv) * ftanh(gv);
            C[idx] = cn;
            hv[e] = fsig(ov) * ftanh(cn);
        }
        uint32_t lo;
        uint32_t hi = pack_hl(hv[0], hv[1], lo);
        const size_t op = ((size_t)(b * 32 + ph) << 12) + y0 * 64 + x;
        oH[op] = hi;
        oL[op] = lo;
    }
}

// 1x1 conv head (64 -> 1) + ReLU; reconstructs h1 = hi + lo from pair planes.
__global__ void head_kernel(const uint32_t* __restrict__ h1h,
                            const uint32_t* __restrict__ h1l,
                            const float* __restrict__ wh,
                            const float* __restrict__ bh,
                            float* __restrict__ out)
{
    int idx = blockIdx.x * blockDim.x + threadIdx.x;   // 65536
    int b   = idx >> 12;
    int pix = idx & 4095;
    float s = bh[0];
#pragma unroll
    for (int ph = 0; ph < 32; ph++) {
        const size_t op = ((size_t)(b * 32 + ph) << 12) + pix;
        uint32_t h = h1h[op], l = h1l[op];
        float v0 = bflo(h) + bflo(l);
        float v1 = bfhi(h) + bfhi(l);
        s = fmaf(wh[2 * ph], v0, s);
        s = fmaf(wh[2 * ph + 1], v1, s);
    }
    out[idx] = fmaxf(s, 0.f);
}

// ------------------------------- launch -------------------------------------

extern "C" void kernel_launch(void* const* d_in, const int* in_sizes, int n_in,
                              void* d_out, int out_size)
{
    const float* x  = (const float*)d_in[0];
    const float* w0 = (const float*)d_in[1];
    const float* b0 = (const float*)d_in[2];
    const float* w1 = (const float*)d_in[3];
    const float* b1 = (const float*)d_in[4];
    const float* wh = (const float*)d_in[5];
    const float* bh = (const float*)d_in[6];
    float* out = (float*)d_out;

    float *c0, *c1;
    uint32_t *h0h, *h0l, *h1h, *h1l, *xph, *xpl, *wh0, *wl0, *wh1, *wl1;
    cudaGetSymbolAddress((void**)&c0,  g_c0);
    cudaGetSymbolAddress((void**)&c1,  g_c1);
    cudaGetSymbolAddress((void**)&h0h, g_h0h);
    cudaGetSymbolAddress((void**)&h0l, g_h0l);
    cudaGetSymbolAddress((void**)&h1h, g_h1h);
    cudaGetSymbolAddress((void**)&h1l, g_h1l);
    cudaGetSymbolAddress((void**)&xph, g_xph);
    cudaGetSymbolAddress((void**)&xpl, g_xpl);
    cudaGetSymbolAddress((void**)&wh0, g_wh0);
    cudaGetSymbolAddress((void**)&wl0, g_wl0);
    cudaGetSymbolAddress((void**)&wh1, g_wh1);
    cudaGetSymbolAddress((void**)&wl1, g_wl1);

    cudaFuncSetAttribute(convlstm_mma<0>,
                         cudaFuncAttributeMaxDynamicSharedMemorySize, DYN_SMEM);
    cudaFuncSetAttribute(convlstm_mma<1>,
                         cudaFuncAttributeMaxDynamicSharedMemorySize, DYN_SMEM);

    zero_state_kernel<<<HSZ / 256, 256>>>();
    build_xpairs<<<16 * 16 * 4096 / 256, 256>>>(x);
    build_w0k<<<(NCH0 * 2048 + 255) / 256, 256>>>(w0);
    build_w1k<<<(NCH1 * 2048 + 255) / 256, 256>>>(w1);

    dim3 grid(64, 16);   // (image row, batch)
    for (int t = 0; t < 16; t++) {
        const int pr = t & 1, pw = (t + 1) & 1;
        // layer 0: pairs = [h0_prev(32) ; x(1)] per tap
        convlstm_mma<0><<<grid, 256, DYN_SMEM>>>(
            wh0, wl0,
            h0h + (size_t)pr * PLSZ, h0l + (size_t)pr * PLSZ,
            xph + (size_t)t * 16 * 4096, xpl + (size_t)t * 16 * 4096,
            b0, c0,
            h0h + (size_t)pw * PLSZ, h0l + (size_t)pw * PLSZ);
        // layer 1: pairs = [h0_new(32) ; h1_prev(32)] per tap
        convlstm_mma<1><<<grid, 256, DYN_SMEM>>>(
            wh1, wl1,
            h0h + (size_t)pw * PLSZ, h0l + (size_t)pw * PLSZ,
            h1h + (size_t)pr * PLSZ, h1l + (size_t)pr * PLSZ,
            b1, c1,
            h1h + (size_t)pw * PLSZ, h1l + (size_t)pw * PLSZ);
    }
    // final h1 in ping-pong slot 0
    head_kernel<<<65536 / 256, 256>>>(h1h, h1l, wh, bh, out);
}

// round 16
// speedup vs baseline: 1.8736x; 1.4144x over previous
#include <cuda_runtime.h>
#include <cuda_fp16.h>
#include <cstdint>

// ---------------------------------------------------------------------------
// ConvLSTM via mma.sync fp16 (A = weights split hi+lo fp16 => ~exact;
// B = states single fp16), 2 MMAs per k16 — 33% less tensor work than the
// bf16 3-term split. sm_103a, compute_103-safe PTX only.
// R16 = R15 pipeline shape: 256 thr, 64 px/CTA, 2 CTAs/SM, chunk16,
// register-staged LDG(c+1) -> compute(c) -> STS(c+1) -> sync.
// States stored as packed fp16x2 channel-pair planes (single precision).
// ---------------------------------------------------------------------------

#define HSZ   (16 * 64 * 64 * 64)     // planar float cell state [b][64][4096]
#define PLSZ  (16 * 32 * 4096)        // pair planes [b][32][4096] (u32)

__device__ float    g_c0[HSZ], g_c1[HSZ];
__device__ uint32_t g_h0p[2][PLSZ], g_h1p[2][PLSZ];
__device__ uint32_t g_xp[16 * 16 * 4096];           // [t][b][px], (x,0) fp16x2

// pre-permuted packed fp16 weight pairs: [chunk16][row 256][pos 8] (u32)
#define NCH0 38
#define NCH1 72
__device__ uint32_t g_wh0[NCH0 * 2048], g_wl0[NCH0 * 2048];
__device__ uint32_t g_wh1[NCH1 * 2048], g_wl1[NCH1 * 2048];

__device__ __forceinline__ float fsig(float x) { return 1.f / (1.f + __expf(-x)); }
__device__ __forceinline__ float ftanh(float x) {
    return 2.f / (1.f + __expf(-2.f * x)) - 1.f;
}

// pack (v0,v1) as fp16x2 hi word; fp16 residuals as lo word (for weights)
__device__ __forceinline__ uint32_t packw_hl(float v0, float v1, uint32_t& lo) {
    __half h0 = __float2half_rn(v0);
    __half h1 = __float2half_rn(v1);
    float r0 = v0 - __half2float(h0);
    float r1 = v1 - __half2float(h1);
    __half2 hh = __halves2half2(h0, h1);
    __half2 ll = __halves2half2(__float2half_rn(r0), __float2half_rn(r1));
    lo = *reinterpret_cast<uint32_t*>(&ll);
    return *reinterpret_cast<uint32_t*>(&hh);
}
__device__ __forceinline__ uint32_t packs(float v0, float v1) {
    __half2 hh = __floats2half2_rn(v0, v1);
    return *reinterpret_cast<uint32_t*>(&hh);
}

#define MMA16816(Cr, Ar, Br) \
    asm volatile("mma.sync.aligned.m16n8k16.row.col.f32.f16.f16.f32 " \
        "{%0,%1,%2,%3}, {%4,%5,%6,%7}, {%8,%9}, {%0,%1,%2,%3};" \
        : "+f"((Cr)[0]), "+f"((Cr)[1]), "+f"((Cr)[2]), "+f"((Cr)[3]) \
        : "r"((Ar)[0]), "r"((Ar)[1]), "r"((Ar)[2]), "r"((Ar)[3]), \
          "r"((Br)[0]), "r"((Br)[1]))

// stored pos p (0..7) -> pair-in-chunk16 u (k-perm [0,4,1,5,2,6,3,7])
__device__ __forceinline__ int pos2u(int p) {
    return (p >> 1) + ((p & 1) << 2);
}

// ------------------------------ prep kernels --------------------------------

__global__ void zero_state_kernel() {
    int i = blockIdx.x * blockDim.x + threadIdx.x;
    if (i < HSZ) { g_c0[i] = 0.f; g_c1[i] = 0.f; }
    if (i < PLSZ) { g_h0p[0][i] = 0u; g_h1p[0][i] = 0u; }
}

__global__ void build_xpairs(const float* __restrict__ x) {
    int idx = blockIdx.x * blockDim.x + threadIdx.x;   // 16*16*4096
    int t  = idx >> 16;
    int b  = (idx >> 12) & 15;
    int px = idx & 4095;
    float v = x[(((size_t)b * 16 + t) << 12) + px];
    g_xp[idx] = packs(v, 0.f);
}

// layer0: gu: kt=gu/33, j=gu%33; j<32 -> ic(1+2j, 2+2j); j==32 -> (x,0)
__global__ void build_w0k(const float* __restrict__ W) {
    int idx = blockIdx.x * blockDim.x + threadIdx.x;   // NCH0*2048
    if (idx >= NCH0 * 2048) return;
    int p  = idx & 7;
    int oc = (idx >> 3) & 255;
    int c  = idx >> 11;
    int gu = c * 8 + pos2u(p);
    float v0 = 0.f, v1 = 0.f;
    if (gu < 297) {
        int kt = gu / 33, j = gu - kt * 33;
        if (j < 32) {
            v0 = W[((size_t)oc * 65 + (1 + 2 * j)) * 9 + kt];
            v1 = W[((size_t)oc * 65 + (2 + 2 * j)) * 9 + kt];
        } else {
            v0 = W[((size_t)oc * 65 + 0) * 9 + kt];
        }
    }
    uint32_t lo;
    uint32_t hi = packw_hl(v0, v1, lo);
    g_wh0[idx] = hi;
    g_wl0[idx] = lo;
}

// layer1: gu: kt=gu>>6, j=gu&63 -> ic (2j, 2j+1)
__global__ void build_w1k(const float* __restrict__ W) {
    int idx = blockIdx.x * blockDim.x + threadIdx.x;   // NCH1*2048
    if (idx >= NCH1 * 2048) return;
    int p  = idx & 7;
    int oc = (idx >> 3) & 255;
    int c  = idx >> 11;
    int gu = c * 8 + pos2u(p);
    int kt = gu >> 6, j = gu & 63;
    float v0 = W[((size_t)oc * 128 + 2 * j) * 9 + kt];
    float v1 = W[((size_t)oc * 128 + 2 * j + 1) * 9 + kt];
    uint32_t lo;
    uint32_t hi = packw_hl(v0, v1, lo);
    g_wh1[idx] = hi;
    g_wl1[idx] = lo;
}

// ------------------------------ main kernel ---------------------------------
// SMEM (u32 units), pitch 12 (48B rows, 16B-aligned), chunk16 double buffer:
//   A_H @ buf*3072 (256 rows)   A_L @ 6144 + buf*3072
//   B   @ 12288 + buf*768 (64 px)
// total 13824 u32 = 55296 B; epilogue float sep[256][65] = 66560 B unions.
#define DYN_SMEM 66560

template <int LAYER>
__global__ void __launch_bounds__(256, 2)
convlstm_mma(const uint32_t* __restrict__ Wh, const uint32_t* __restrict__ Wl,
             const uint32_t* __restrict__ pA,   // first 32 pairs planes
             const uint32_t* __restrict__ pB2,  // x plane (L0) / h1_prev (L1)
             const float* __restrict__ bias,
             float* __restrict__ C,
             uint32_t* __restrict__ oP)
{
    constexpr int PPT = (LAYER == 0) ? 33 : 64;      // pairs per tap
    constexpr int NCH = (LAYER == 0) ? NCH0 : NCH1;
    extern __shared__ uint32_t sm[];
    float* sep = (float*)sm;

    const int tid = threadIdx.x;
    const int wid = tid >> 5;
    const int lid = tid & 31;
    const int g   = lid >> 2;
    const int t4  = lid & 3;
    const int b   = blockIdx.y;
    const int y0  = blockIdx.x;

    float acc[2][8][4];
#pragma unroll
    for (int i = 0; i < 2; i++)
#pragma unroll
        for (int j = 0; j < 8; j++)
#pragma unroll
            for (int k = 0; k < 4; k++) acc[i][j][k] = 0.f;

    const int bpx = tid & 63;          // pixel x for B staging
    const int bu  = tid >> 6;          // 0..3: handles pos bu, bu+4

    // ---- pipeline registers ----
    uint4 pah0, pah1, pal0, pal1;      // A chunk prefetch (hi 8 u32, lo 8 u32)
    uint32_t pb[2];                    // B chunk prefetch (single precision)

    auto ldg_stage = [&](int c) {
        const uint4* sH = (const uint4*)(Wh + (size_t)c * 2048) + tid * 2;
        const uint4* sL = (const uint4*)(Wl + (size_t)c * 2048) + tid * 2;
        pah0 = sH[0]; pah1 = sH[1];
        pal0 = sL[0]; pal1 = sL[1];
#pragma unroll
        for (int s = 0; s < 2; s++) {
            const int pos = bu + 4 * s;
            const int gu  = c * 8 + pos2u(pos);
            const int kt  = gu / PPT;
            const int j   = gu - kt * PPT;
            const int ky  = kt / 3;
            const int kx  = kt - ky * 3;
            const int y   = y0 + ky - 1;
            const int x   = bpx + kx - 1;
            const bool ok = ((unsigned)y < 64u) && ((unsigned)x < 64u);
            const int poff = y * 64 + x;
            const uint32_t* src;
            if (j < 32) {
                src = pA + ((size_t)(b * 32 + j) << 12);
            } else if (LAYER == 0) {
                src = pB2 + ((size_t)b << 12);                    // x plane
            } else {
                src = pB2 + ((size_t)(b * 32 + j - 32) << 12);    // h1_prev
            }
            pb[s] = ok ? __ldg(src + poff) : 0u;
        }
    };

    auto sts_stage = [&](int buf) {
        uint32_t* dH = sm + buf * 3072 + tid * 12;
        uint32_t* dL = sm + 6144 + buf * 3072 + tid * 12;
        ((uint4*)dH)[0] = pah0; ((uint4*)dH)[1] = pah1;
        ((uint4*)dL)[0] = pal0; ((uint4*)dL)[1] = pal1;
        uint32_t* bP = sm + 12288 + buf * 768 + bpx * 12;
        bP[bu]     = pb[0];
        bP[bu + 4] = pb[1];
    };

    // ---- prologue ----
    ldg_stage(0);
    sts_stage(0);
    __syncthreads();

    // ---- main loop: LDG(c+1) early, compute(c), STS(c+1), sync ----
    for (int c = 0; c < NCH; c++) {
        if (c + 1 < NCH) ldg_stage(c + 1);

        const int buf = c & 1;
        const uint32_t* asH = sm + buf * 3072;
        const uint32_t* asL = sm + 6144 + buf * 3072;
        const uint32_t* bs  = sm + 12288 + buf * 768;

        uint32_t aH[2][4], aL[2][4];
#pragma unroll
        for (int ma = 0; ma < 2; ma++) {
            const int row = wid * 32 + 16 * ma + g;
            uint2 p  = *(const uint2*)(asH + row * 12 + 2 * t4);
            uint2 q  = *(const uint2*)(asH + (row + 8) * 12 + 2 * t4);
            aH[ma][0] = p.x;  aH[ma][1] = q.x;
            aH[ma][2] = p.y;  aH[ma][3] = q.y;
            uint2 pl = *(const uint2*)(asL + row * 12 + 2 * t4);
            uint2 ql = *(const uint2*)(asL + (row + 8) * 12 + 2 * t4);
            aL[ma][0] = pl.x; aL[ma][1] = ql.x;
            aL[ma][2] = pl.y; aL[ma][3] = ql.y;
        }
#pragma unroll
        for (int h = 0; h < 2; h++) {
            uint32_t bF[4][2];
#pragma unroll
            for (int na = 0; na < 4; na++) {
                const int col = 8 * (4 * h + na) + g;
                uint2 pb2 = *(const uint2*)(bs + col * 12 + 2 * t4);
                bF[na][0] = pb2.x; bF[na][1] = pb2.y;
            }
#pragma unroll
            for (int ma = 0; ma < 2; ma++)
#pragma unroll
                for (int na = 0; na < 4; na++) {
                    MMA16816(acc[ma][4 * h + na], aH[ma], bF[na]);
                    MMA16816(acc[ma][4 * h + na], aL[ma], bF[na]);
                }
        }

        if (c + 1 < NCH) sts_stage((c + 1) & 1);
        __syncthreads();
    }

    // ---- epilogue: transpose to sep[256][65], fused LSTM, fp16x2 plane out --
#pragma unroll
    for (int ma = 0; ma < 2; ma++)
#pragma unroll
        for (int na = 0; na < 8; na++) {
            const int row = wid * 32 + 16 * ma + g;
            const int col = 8 * na + 2 * t4;
            sep[row * 65 + col]           = acc[ma][na][0];
            sep[row * 65 + col + 1]       = acc[ma][na][1];
            sep[(row + 8) * 65 + col]     = acc[ma][na][2];
            sep[(row + 8) * 65 + col + 1] = acc[ma][na][3];
        }
    __syncthreads();

#pragma unroll
    for (int j = 0; j < 8; j++) {
        const int item = tid + 256 * j;        // 0..2047 = (ph 0..31, x 0..63)
        const int ph = item >> 6;
        const int x  = item & 63;
        float hv[2];
#pragma unroll
        for (int e = 0; e < 2; e++) {
            const int hid = 2 * ph + e;
            const float iv = sep[hid * 65 + x]         + bias[hid];
            const float fv = sep[(64 + hid) * 65 + x]  + bias[64 + hid];
            const float ov = sep[(128 + hid) * 65 + x] + bias[128 + hid];
            const float gv = sep[(192 + hid) * 65 + x] + bias[192 + hid];
            const size_t idx = (((size_t)b * 64 + hid) << 12) + y0 * 64 + x;
            const float cn = fsig(fv) * C[idx] + fsig(iv) * ftanh(gv);
            C[idx] = cn;
            hv[e] = fsig(ov) * ftanh(cn);
        }
        const size_t op = ((size_t)(b * 32 + ph) << 12) + y0 * 64 + x;
        oP[op] = packs(hv[0], hv[1]);
    }
}

// 1x1 conv head (64 -> 1) + ReLU over final h1 (fp16x2 pair planes).
__global__ void head_kernel(const uint32_t* __restrict__ h1p,
                            const float* __restrict__ wh,
                            const float* __restrict__ bh,
                            float* __restrict__ out)
{
    int idx = blockIdx.x * blockDim.x + threadIdx.x;   // 65536
    int b   = idx >> 12;
    int pix = idx & 4095;
    float s = bh[0];
#pragma unroll
    for (int ph = 0; ph < 32; ph++) {
        const size_t op = ((size_t)(b * 32 + ph) << 12) + pix;
        uint32_t u = h1p[op];
        __half2 hp = *reinterpret_cast<__half2*>(&u);
        s = fmaf(wh[2 * ph],     __low2float(hp),  s);
        s = fmaf(wh[2 * ph + 1], __high2float(hp), s);
    }
    out[idx] = fmaxf(s, 0.f);
}

// ------------------------------- launch -------------------------------------

extern "C" void kernel_launch(void* const* d_in, const int* in_sizes, int n_in,
                              void* d_out, int out_size)
{
    const float* x  = (const float*)d_in[0];
    const float* w0 = (const float*)d_in[1];
    const float* b0 = (const float*)d_in[2];
    const float* w1 = (const float*)d_in[3];
    const float* b1 = (const float*)d_in[4];
    const float* wh = (const float*)d_in[5];
    const float* bh = (const float*)d_in[6];
    float* out = (float*)d_out;

    float *c0, *c1;
    uint32_t *h0p, *h1p, *xp, *wh0, *wl0, *wh1, *wl1;
    cudaGetSymbolAddress((void**)&c0,  g_c0);
    cudaGetSymbolAddress((void**)&c1,  g_c1);
    cudaGetSymbolAddress((void**)&h0p, g_h0p);
    cudaGetSymbolAddress((void**)&h1p, g_h1p);
    cudaGetSymbolAddress((void**)&xp,  g_xp);
    cudaGetSymbolAddress((void**)&wh0, g_wh0);
    cudaGetSymbolAddress((void**)&wl0, g_wl0);
    cudaGetSymbolAddress((void**)&wh1, g_wh1);
    cudaGetSymbolAddress((void**)&wl1, g_wl1);

    cudaFuncSetAttribute(convlstm_mma<0>,
                         cudaFuncAttributeMaxDynamicSharedMemorySize, DYN_SMEM);
    cudaFuncSetAttribute(convlstm_mma<1>,
                         cudaFuncAttributeMaxDynamicSharedMemorySize, DYN_SMEM);

    zero_state_kernel<<<HSZ / 256, 256>>>();
    build_xpairs<<<16 * 16 * 4096 / 256, 256>>>(x);
    build_w0k<<<(NCH0 * 2048 + 255) / 256, 256>>>(w0);
    build_w1k<<<(NCH1 * 2048 + 255) / 256, 256>>>(w1);

    dim3 grid(64, 16);   // (image row, batch)
    for (int t = 0; t < 16; t++) {
        const int pr = t & 1, pw = (t + 1) & 1;
        // layer 0: pairs = [h0_prev(32) ; x(1)] per tap
        convlstm_mma<0><<<grid, 256, DYN_SMEM>>>(
            wh0, wl0,
            h0p + (size_t)pr * PLSZ,
            xp + (size_t)t * 16 * 4096,
            b0, c0,
            h0p + (size_t)pw * PLSZ);
        // layer 1: pairs = [h0_new(32) ; h1_prev(32)] per tap
        convlstm_mma<1><<<grid, 256, DYN_SMEM>>>(
            wh1, wl1,
            h0p + (size_t)pw * PLSZ,
            h1p + (size_t)pr * PLSZ,
            b1, c1,
            h1p + (size_t)pw * PLSZ);
    }
    // final h1 in ping-pong slot 0
    head_kernel<<<65536 / 256, 256>>>(h1p, wh, bh, out);
}

// round 17
// speedup vs baseline: 2.5567x; 1.3646x over previous
#include <cuda_runtime.h>
#include <cuda_fp16.h>
#include <cstdint>

// ---------------------------------------------------------------------------
// ConvLSTM via mma.sync fp16, SINGLE-TERM: A = weights fp16, B = states fp16,
// 1 MMA per k16 (half of R16's 2-term). rel_err budget: ~1.5e-4 expected vs
// 1e-3 gate. sm_103a, compute_103-safe PTX only.
// R17 = R15/R16 pipeline shape: 256 thr, 64 px/CTA, 2 CTAs/SM, chunk16,
// register-staged LDG(c+1) -> compute(c) -> STS(c+1) -> sync.
// States stored as packed fp16x2 channel-pair planes.
// ---------------------------------------------------------------------------

#define HSZ   (16 * 64 * 64 * 64)     // planar float cell state [b][64][4096]
#define PLSZ  (16 * 32 * 4096)        // pair planes [b][32][4096] (u32)

__device__ float    g_c0[HSZ], g_c1[HSZ];
__device__ uint32_t g_h0p[2][PLSZ], g_h1p[2][PLSZ];
__device__ uint32_t g_xp[16 * 16 * 4096];           // [t][b][px], (x,0) fp16x2

// pre-permuted packed fp16 weight pairs: [chunk16][row 256][pos 8] (u32)
#define NCH0 38
#define NCH1 72
__device__ uint32_t g_w0[NCH0 * 2048];
__device__ uint32_t g_w1[NCH1 * 2048];

__device__ __forceinline__ float fsig(float x) { return 1.f / (1.f + __expf(-x)); }
__device__ __forceinline__ float ftanh(float x) {
    return 2.f / (1.f + __expf(-2.f * x)) - 1.f;
}

__device__ __forceinline__ uint32_t packs(float v0, float v1) {
    __half2 hh = __floats2half2_rn(v0, v1);
    return *reinterpret_cast<uint32_t*>(&hh);
}

#define MMA16816(Cr, Ar, Br) \
    asm volatile("mma.sync.aligned.m16n8k16.row.col.f32.f16.f16.f32 " \
        "{%0,%1,%2,%3}, {%4,%5,%6,%7}, {%8,%9}, {%0,%1,%2,%3};" \
        : "+f"((Cr)[0]), "+f"((Cr)[1]), "+f"((Cr)[2]), "+f"((Cr)[3]) \
        : "r"((Ar)[0]), "r"((Ar)[1]), "r"((Ar)[2]), "r"((Ar)[3]), \
          "r"((Br)[0]), "r"((Br)[1]))

// stored pos p (0..7) -> pair-in-chunk16 u (k-perm [0,4,1,5,2,6,3,7])
__device__ __forceinline__ int pos2u(int p) {
    return (p >> 1) + ((p & 1) << 2);
}

// ------------------------------ prep kernels --------------------------------

__global__ void zero_state_kernel() {
    int i = blockIdx.x * blockDim.x + threadIdx.x;
    if (i < HSZ) { g_c0[i] = 0.f; g_c1[i] = 0.f; }
    if (i < PLSZ) { g_h0p[0][i] = 0u; g_h1p[0][i] = 0u; }
}

__global__ void build_xpairs(const float* __restrict__ x) {
    int idx = blockIdx.x * blockDim.x + threadIdx.x;   // 16*16*4096
    int t  = idx >> 16;
    int b  = (idx >> 12) & 15;
    int px = idx & 4095;
    float v = x[(((size_t)b * 16 + t) << 12) + px];
    g_xp[idx] = packs(v, 0.f);
}

// layer0: gu: kt=gu/33, j=gu%33; j<32 -> ic(1+2j, 2+2j); j==32 -> (x,0)
__global__ void build_w0k(const float* __restrict__ W) {
    int idx = blockIdx.x * blockDim.x + threadIdx.x;   // NCH0*2048
    if (idx >= NCH0 * 2048) return;
    int p  = idx & 7;
    int oc = (idx >> 3) & 255;
    int c  = idx >> 11;
    int gu = c * 8 + pos2u(p);
    float v0 = 0.f, v1 = 0.f;
    if (gu < 297) {
        int kt = gu / 33, j = gu - kt * 33;
        if (j < 32) {
            v0 = W[((size_t)oc * 65 + (1 + 2 * j)) * 9 + kt];
            v1 = W[((size_t)oc * 65 + (2 + 2 * j)) * 9 + kt];
        } else {
            v0 = W[((size_t)oc * 65 + 0) * 9 + kt];
        }
    }
    g_w0[idx] = packs(v0, v1);
}

// layer1: gu: kt=gu>>6, j=gu&63 -> ic (2j, 2j+1)
__global__ void build_w1k(const float* __restrict__ W) {
    int idx = blockIdx.x * blockDim.x + threadIdx.x;   // NCH1*2048
    if (idx >= NCH1 * 2048) return;
    int p  = idx & 7;
    int oc = (idx >> 3) & 255;
    int c  = idx >> 11;
    int gu = c * 8 + pos2u(p);
    int kt = gu >> 6, j = gu & 63;
    float v0 = W[((size_t)oc * 128 + 2 * j) * 9 + kt];
    float v1 = W[((size_t)oc * 128 + 2 * j + 1) * 9 + kt];
    g_w1[idx] = packs(v0, v1);
}

// ------------------------------ main kernel ---------------------------------
// SMEM (u32 units), pitch 12 (48B rows, 16B-aligned), chunk16 double buffer:
//   A @ buf*3072 (256 rows)
//   B @ 6144 + buf*768 (64 px)
// total 7680 u32 = 30720 B; epilogue float sep[256][65] = 66560 B unions.
#define DYN_SMEM 66560

template <int LAYER>
__global__ void __launch_bounds__(256, 2)
convlstm_mma(const uint32_t* __restrict__ Wp,
             const uint32_t* __restrict__ pA,   // first 32 pairs planes
             const uint32_t* __restrict__ pB2,  // x plane (L0) / h1_prev (L1)
             const float* __restrict__ bias,
             float* __restrict__ C,
             uint32_t* __restrict__ oP)
{
    constexpr int PPT = (LAYER == 0) ? 33 : 64;      // pairs per tap
    constexpr int NCH = (LAYER == 0) ? NCH0 : NCH1;
    extern __shared__ uint32_t sm[];
    float* sep = (float*)sm;

    const int tid = threadIdx.x;
    const int wid = tid >> 5;
    const int lid = tid & 31;
    const int g   = lid >> 2;
    const int t4  = lid & 3;
    const int b   = blockIdx.y;
    const int y0  = blockIdx.x;

    float acc[2][8][4];
#pragma unroll
    for (int i = 0; i < 2; i++)
#pragma unroll
        for (int j = 0; j < 8; j++)
#pragma unroll
            for (int k = 0; k < 4; k++) acc[i][j][k] = 0.f;

    const int bpx = tid & 63;          // pixel x for B staging
    const int bu  = tid >> 6;          // 0..3: handles pos bu, bu+4

    // ---- pipeline registers ----
    uint4 pa0, pa1;                    // A chunk prefetch (8 u32)
    uint32_t pb[2];                    // B chunk prefetch

    auto ldg_stage = [&](int c) {
        const uint4* sA = (const uint4*)(Wp + (size_t)c * 2048) + tid * 2;
        pa0 = sA[0]; pa1 = sA[1];
#pragma unroll
        for (int s = 0; s < 2; s++) {
            const int pos = bu + 4 * s;
            const int gu  = c * 8 + pos2u(pos);
            const int kt  = gu / PPT;
            const int j   = gu - kt * PPT;
            const int ky  = kt / 3;
            const int kx  = kt - ky * 3;
            const int y   = y0 + ky - 1;
            const int x   = bpx + kx - 1;
            const bool ok = ((unsigned)y < 64u) && ((unsigned)x < 64u);
            const int poff = y * 64 + x;
            const uint32_t* src;
            if (j < 32) {
                src = pA + ((size_t)(b * 32 + j) << 12);
            } else if (LAYER == 0) {
                src = pB2 + ((size_t)b << 12);                    // x plane
            } else {
                src = pB2 + ((size_t)(b * 32 + j - 32) << 12);    // h1_prev
            }
            pb[s] = ok ? __ldg(src + poff) : 0u;
        }
    };

    auto sts_stage = [&](int buf) {
        uint32_t* dA = sm + buf * 3072 + tid * 12;
        ((uint4*)dA)[0] = pa0; ((uint4*)dA)[1] = pa1;
        uint32_t* bP = sm + 6144 + buf * 768 + bpx * 12;
        bP[bu]     = pb[0];
        bP[bu + 4] = pb[1];
    };

    // ---- prologue ----
    ldg_stage(0);
    sts_stage(0);
    __syncthreads();

    // ---- main loop: LDG(c+1) early, compute(c), STS(c+1), sync ----
    for (int c = 0; c < NCH; c++) {
        if (c + 1 < NCH) ldg_stage(c + 1);

        const int buf = c & 1;
        const uint32_t* as = sm + buf * 3072;
        const uint32_t* bs = sm + 6144 + buf * 768;

        uint32_t aF[2][4];
#pragma unroll
        for (int ma = 0; ma < 2; ma++) {
            const int row = wid * 32 + 16 * ma + g;
            uint2 p  = *(const uint2*)(as + row * 12 + 2 * t4);
            uint2 q  = *(const uint2*)(as + (row + 8) * 12 + 2 * t4);
            aF[ma][0] = p.x;  aF[ma][1] = q.x;
            aF[ma][2] = p.y;  aF[ma][3] = q.y;
        }
#pragma unroll
        for (int h = 0; h < 2; h++) {
            uint32_t bF[4][2];
#pragma unroll
            for (int na = 0; na < 4; na++) {
                const int col = 8 * (4 * h + na) + g;
                uint2 pb2 = *(const uint2*)(bs + col * 12 + 2 * t4);
                bF[na][0] = pb2.x; bF[na][1] = pb2.y;
            }
#pragma unroll
            for (int ma = 0; ma < 2; ma++)
#pragma unroll
                for (int na = 0; na < 4; na++)
                    MMA16816(acc[ma][4 * h + na], aF[ma], bF[na]);
        }

        if (c + 1 < NCH) sts_stage((c + 1) & 1);
        __syncthreads();
    }

    // ---- epilogue: transpose to sep[256][65], fused LSTM, fp16x2 plane out --
#pragma unroll
    for (int ma = 0; ma < 2; ma++)
#pragma unroll
        for (int na = 0; na < 8; na++) {
            const int row = wid * 32 + 16 * ma + g;
            const int col = 8 * na + 2 * t4;
            sep[row * 65 + col]           = acc[ma][na][0];
            sep[row * 65 + col + 1]       = acc[ma][na][1];
            sep[(row + 8) * 65 + col]     = acc[ma][na][2];
            sep[(row + 8) * 65 + col + 1] = acc[ma][na][3];
        }
    __syncthreads();

#pragma unroll
    for (int j = 0; j < 8; j++) {
        const int item = tid + 256 * j;        // 0..2047 = (ph 0..31, x 0..63)
        const int ph = item >> 6;
        const int x  = item & 63;
        float hv[2];
#pragma unroll
        for (int e = 0; e < 2; e++) {
            const int hid = 2 * ph + e;
            const float iv = sep[hid * 65 + x]         + bias[hid];
            const float fv = sep[(64 + hid) * 65 + x]  + bias[64 + hid];
            const float ov = sep[(128 + hid) * 65 + x] + bias[128 + hid];
            const float gv = sep[(192 + hid) * 65 + x] + bias[192 + hid];
            const size_t idx = (((size_t)b * 64 + hid) << 12) + y0 * 64 + x;
            const float cn = fsig(fv) * C[idx] + fsig(iv) * ftanh(gv);
            C[idx] = cn;
            hv[e] = fsig(ov) * ftanh(cn);
        }
        const size_t op = ((size_t)(b * 32 + ph) << 12) + y0 * 64 + x;
        oP[op] = packs(hv[0], hv[1]);
    }
}

// 1x1 conv head (64 -> 1) + ReLU over final h1 (fp16x2 pair planes).
__global__ void head_kernel(const uint32_t* __restrict__ h1p,
                            const float* __restrict__ wh,
                            const float* __restrict__ bh,
                            float* __restrict__ out)
{
    int idx = blockIdx.x * blockDim.x + threadIdx.x;   // 65536
    int b   = idx >> 12;
    int pix = idx & 4095;
    float s = bh[0];
#pragma unroll
    for (int ph = 0; ph < 32; ph++) {
        const size_t op = ((size_t)(b * 32 + ph) << 12) + pix;
        uint32_t u = h1p[op];
        __half2 hp = *reinterpret_cast<__half2*>(&u);
        s = fmaf(wh[2 * ph],     __low2float(hp),  s);
        s = fmaf(wh[2 * ph + 1], __high2float(hp), s);
    }
    out[idx] = fmaxf(s, 0.f);
}

// ------------------------------- launch -------------------------------------

extern "C" void kernel_launch(void* const* d_in, const int* in_sizes, int n_in,
                              void* d_out, int out_size)
{
    const float* x  = (const float*)d_in[0];
    const float* w0 = (const float*)d_in[1];
    const float* b0 = (const float*)d_in[2];
    const float* w1 = (const float*)d_in[3];
    const float* b1 = (const float*)d_in[4];
    const float* wh = (const float*)d_in[5];
    const float* bh = (const float*)d_in[6];
    float* out = (float*)d_out;

    float *c0, *c1;
    uint32_t *h0p, *h1p, *xp, *w0p, *w1p;
    cudaGetSymbolAddress((void**)&c0,  g_c0);
    cudaGetSymbolAddress((void**)&c1,  g_c1);
    cudaGetSymbolAddress((void**)&h0p, g_h0p);
    cudaGetSymbolAddress((void**)&h1p, g_h1p);
    cudaGetSymbolAddress((void**)&xp,  g_xp);
    cudaGetSymbolAddress((void**)&w0p, g_w0);
    cudaGetSymbolAddress((void**)&w1p, g_w1);

    cudaFuncSetAttribute(convlstm_mma<0>,
                         cudaFuncAttributeMaxDynamicSharedMemorySize, DYN_SMEM);
    cudaFuncSetAttribute(convlstm_mma<1>,
                         cudaFuncAttributeMaxDynamicSharedMemorySize, DYN_SMEM);

    zero_state_kernel<<<HSZ / 256, 256>>>();
    build_xpairs<<<16 * 16 * 4096 / 256, 256>>>(x);
    build_w0k<<<(NCH0 * 2048 + 255) / 256, 256>>>(w0);
    build_w1k<<<(NCH1 * 2048 + 255) / 256, 256>>>(w1);

    dim3 grid(64, 16);   // (image row, batch)
    for (int t = 0; t < 16; t++) {
        const int pr = t & 1, pw = (t + 1) & 1;
        // layer 0: pairs = [h0_prev(32) ; x(1)] per tap
        convlstm_mma<0><<<grid, 256, DYN_SMEM>>>(
            w0p,
            h0p + (size_t)pr * PLSZ,
            xp + (size_t)t * 16 * 4096,
            b0, c0,
            h0p + (size_t)pw * PLSZ);
        // layer 1: pairs = [h0_new(32) ; h1_prev(32)] per tap
        convlstm_mma<1><<<grid, 256, DYN_SMEM>>>(
            w1p,
            h0p + (size_t)pw * PLSZ,
            h1p + (size_t)pr * PLSZ,
            b1, c1,
            h1p + (size_t)pw * PLSZ);
    }
    // final h1 in ping-pong slot 0
    head_kernel<<<65536 / 256, 256>>>(h1p, wh, bh, out);
}